// round 3
// baseline (speedup 1.0000x reference)
#include <cuda_runtime.h>
#include <cuda_bf16.h>
#include <math.h>

// Problem constants
#define NB 8          // batch
#define CC 1024       // channels in/out
#define CID 512       // inner channels
#define NN 3136       // H*W
#define ROWS_TOT (NB * NN)          // 25088
#define BN_CHUNKS 98                // 25088 / 256

// ---------------- device scratch (static, allowed) ----------------
__device__ float g_th[(size_t)NB * NN * CID];   // (B,N,CI)
__device__ float g_ph[(size_t)NB * NN * CID];
__device__ float g_gx[(size_t)NB * NN * CID];
__device__ float g_f [(size_t)NB * NN * NN];    // (B,N,N)  attention scores / probs
__device__ float g_y [(size_t)NB * NN * CID];
__device__ float g_wy[(size_t)NB * NN * CC];    // (B,N,C)
__device__ float g_part[BN_CHUNKS * CC * 2];    // partial (sum, sumsq)
__device__ float g_ab[CC * 2];                  // per-channel (scale, shift)

// =====================================================================
// Generic 128x128x16 register-blocked fp32 GEMM.
//   C(m,n) = sum_k A(m,k)*B(k,n) [+ bias(n)]
// AKC:  A(m,k) = A[m*lda + k]  (K contiguous)   else A[k*lda + m]
// BKC:  B(k,n) = B[n*ldb + k]  (K contiguous)   else B[k*ldb + n]
// blockIdx.z = batch, per-operand element strides.
// All K dims here are multiples of 16; M,N multiples of 4 (edge handling
// zero-fills loads / guards stores).
// =====================================================================
template<bool AKC, bool BKC, bool HAS_BIAS>
__global__ void __launch_bounds__(256)
gemm128(const float* __restrict__ A, int lda, size_t strideA,
        const float* __restrict__ B, int ldb, size_t strideB,
        float* __restrict__ C, int ldc, size_t strideC,
        int M, int N, int K, const float* __restrict__ bias)
{
    __shared__ float As[16][128];
    __shared__ float Bs[16][128];

    const int bz = blockIdx.z;
    A += (size_t)bz * strideA;
    B += (size_t)bz * strideB;
    C += (size_t)bz * strideC;

    const int m0 = blockIdx.y * 128;
    const int n0 = blockIdx.x * 128;
    const int t  = threadIdx.x;
    const int tx = t & 15;   // column group
    const int ty = t >> 4;   // row group

    float acc[8][8];
#pragma unroll
    for (int i = 0; i < 8; i++)
#pragma unroll
        for (int j = 0; j < 8; j++) acc[i][j] = 0.f;

    for (int k0 = 0; k0 < K; k0 += 16) {
        // ---- A tile ----
        if (AKC) {
#pragma unroll
            for (int i = 0; i < 2; i++) {
                int idx = t + i * 256;
                int kk  = (idx & 3) * 4;
                int mm  = idx >> 2;
                float4 v = make_float4(0.f, 0.f, 0.f, 0.f);
                if (m0 + mm < M)
                    v = *(const float4*)(A + (size_t)(m0 + mm) * lda + (k0 + kk));
                As[kk + 0][mm] = v.x; As[kk + 1][mm] = v.y;
                As[kk + 2][mm] = v.z; As[kk + 3][mm] = v.w;
            }
        } else {
#pragma unroll
            for (int i = 0; i < 2; i++) {
                int idx = t + i * 256;
                int mm  = (idx & 31) * 4;
                int kk  = idx >> 5;
                float4 v = make_float4(0.f, 0.f, 0.f, 0.f);
                if (m0 + mm < M)
                    v = *(const float4*)(A + (size_t)(k0 + kk) * lda + (m0 + mm));
                *(float4*)&As[kk][mm] = v;
            }
        }
        // ---- B tile ----
        if (BKC) {
#pragma unroll
            for (int i = 0; i < 2; i++) {
                int idx = t + i * 256;
                int kk  = (idx & 3) * 4;
                int nn  = idx >> 2;
                float4 v = make_float4(0.f, 0.f, 0.f, 0.f);
                if (n0 + nn < N)
                    v = *(const float4*)(B + (size_t)(n0 + nn) * ldb + (k0 + kk));
                Bs[kk + 0][nn] = v.x; Bs[kk + 1][nn] = v.y;
                Bs[kk + 2][nn] = v.z; Bs[kk + 3][nn] = v.w;
            }
        } else {
#pragma unroll
            for (int i = 0; i < 2; i++) {
                int idx = t + i * 256;
                int nn  = (idx & 31) * 4;
                int kk  = idx >> 5;
                float4 v = make_float4(0.f, 0.f, 0.f, 0.f);
                if (n0 + nn < N)
                    v = *(const float4*)(B + (size_t)(k0 + kk) * ldb + (n0 + nn));
                *(float4*)&Bs[kk][nn] = v;
            }
        }
        __syncthreads();

#pragma unroll
        for (int k = 0; k < 16; k++) {
            float a[8], b[8];
            *(float4*)&a[0] = *(const float4*)&As[k][ty * 8];
            *(float4*)&a[4] = *(const float4*)&As[k][ty * 8 + 4];
            *(float4*)&b[0] = *(const float4*)&Bs[k][tx * 8];
            *(float4*)&b[4] = *(const float4*)&Bs[k][tx * 8 + 4];
#pragma unroll
            for (int i = 0; i < 8; i++)
#pragma unroll
                for (int j = 0; j < 8; j++)
                    acc[i][j] = fmaf(a[i], b[j], acc[i][j]);
        }
        __syncthreads();
    }

    // ---- epilogue ----
#pragma unroll
    for (int i = 0; i < 8; i++) {
        int row = m0 + ty * 8 + i;
        if (row >= M) continue;
#pragma unroll
        for (int j = 0; j < 8; j++) {
            int col = n0 + tx * 8 + j;
            if (col < N) {
                float v = acc[i][j];
                if (HAS_BIAS) v += bias[col];
                C[(size_t)row * ldc + col] = v;
            }
        }
    }
}

// =====================================================================
// Row softmax over length NN (one block per row)
// =====================================================================
__global__ void __launch_bounds__(256)
softmax_rows(float* __restrict__ F)
{
    __shared__ float buf[NN];
    __shared__ float red[256];
    const size_t row = blockIdx.x;
    float* __restrict__ p = F + row * (size_t)NN;
    const int t = threadIdx.x;

    float m = -3.402823466e38f;
    for (int i = t; i < NN; i += 256) {
        float v = p[i];
        buf[i] = v;
        m = fmaxf(m, v);
    }
    red[t] = m; __syncthreads();
    for (int s = 128; s > 0; s >>= 1) {
        if (t < s) red[t] = fmaxf(red[t], red[t + s]);
        __syncthreads();
    }
    m = red[0];
    __syncthreads();

    float sum = 0.f;
    for (int i = t; i < NN; i += 256) {
        float e = __expf(buf[i] - m);
        buf[i] = e;
        sum += e;
    }
    red[t] = sum; __syncthreads();
    for (int s = 128; s > 0; s >>= 1) {
        if (t < s) red[t] += red[t + s];
        __syncthreads();
    }
    float inv = 1.f / red[0];
    for (int i = t; i < NN; i += 256) p[i] = buf[i] * inv;
}

// =====================================================================
// BatchNorm statistics: two-stage deterministic reduction
// =====================================================================
__global__ void __launch_bounds__(256)
bn_partial(const float* __restrict__ wy)
{
    int c = blockIdx.x * 256 + threadIdx.x;   // channel 0..1023
    int chunk = blockIdx.y;                   // 0..97
    int r0 = chunk * 256;
    float s = 0.f, s2 = 0.f;
    for (int r = r0; r < r0 + 256; r++) {
        float v = wy[(size_t)r * CC + c];
        s += v; s2 += v * v;
    }
    g_part[((size_t)chunk * CC + c) * 2 + 0] = s;
    g_part[((size_t)chunk * CC + c) * 2 + 1] = s2;
}

__global__ void __launch_bounds__(256)
bn_finalize(const float* __restrict__ gamma, const float* __restrict__ beta)
{
    int c = blockIdx.x * 256 + threadIdx.x;
    float s = 0.f, s2 = 0.f;
    for (int ch = 0; ch < BN_CHUNKS; ch++) {
        s  += g_part[((size_t)ch * CC + c) * 2 + 0];
        s2 += g_part[((size_t)ch * CC + c) * 2 + 1];
    }
    const float invR = 1.f / (float)ROWS_TOT;
    float mu  = s * invR;
    float var = s2 * invR - mu * mu;
    float a = gamma[c] * rsqrtf(var + 1e-5f);
    g_ab[c * 2 + 0] = a;
    g_ab[c * 2 + 1] = beta[c] - mu * a;
}

// =====================================================================
// normalize + residual + NHWC->NCHW transpose (32x32 smem tiles)
// =====================================================================
__global__ void __launch_bounds__(256)
out_kernel(const float* __restrict__ wy, const float* __restrict__ x1,
           float* __restrict__ out)
{
    __shared__ float tile[32][33];
    int b  = blockIdx.z;
    int n0 = blockIdx.x * 32;
    int c0 = blockIdx.y * 32;
    int tx = threadIdx.x, ty = threadIdx.y;

    for (int i = ty; i < 32; i += 8) {
        int c = c0 + tx, n = n0 + i;
        float v = wy[((size_t)b * NN + n) * CC + c];
        tile[i][tx] = v * g_ab[c * 2 + 0] + g_ab[c * 2 + 1];
    }
    __syncthreads();
    for (int i = ty; i < 32; i += 8) {
        int c = c0 + i, n = n0 + tx;
        size_t idx = ((size_t)b * CC + c) * (size_t)NN + n;
        out[idx] = tile[tx][i] + x1[idx];
    }
}

// =====================================================================
// launcher
// =====================================================================
extern "C" void kernel_launch(void* const* d_in, const int* in_sizes, int n_in,
                              void* d_out, int out_size)
{
    const float* x1   = (const float*)d_in[0];
    const float* x2   = (const float*)d_in[1];
    const float* g_w  = (const float*)d_in[2];
    const float* g_b  = (const float*)d_in[3];
    const float* th_w = (const float*)d_in[4];
    const float* th_b = (const float*)d_in[5];
    const float* ph_w = (const float*)d_in[6];
    const float* ph_b = (const float*)d_in[7];
    const float* wz_w = (const float*)d_in[8];
    const float* wz_b = (const float*)d_in[9];
    const float* gam  = (const float*)d_in[10];
    const float* bet  = (const float*)d_in[11];
    float* out = (float*)d_out;

    float *th, *ph, *gx, *f, *y, *wy;
    cudaGetSymbolAddress((void**)&th, g_th);
    cudaGetSymbolAddress((void**)&ph, g_ph);
    cudaGetSymbolAddress((void**)&gx, g_gx);
    cudaGetSymbolAddress((void**)&f,  g_f);
    cudaGetSymbolAddress((void**)&y,  g_y);
    cudaGetSymbolAddress((void**)&wy, g_wy);

    const size_t strideX  = (size_t)CC * NN;     // per-batch x1/x2
    const size_t strideP  = (size_t)NN * CID;    // per-batch th/ph/gx/y
    const size_t strideF  = (size_t)NN * NN;     // per-batch scores
    const size_t strideWY = (size_t)NN * CC;     // per-batch wy

    dim3 blk(256);

    // projections: (N x C) @ (C x CI) per batch, A = X (k-strided), B = W (K contig)
    dim3 gProj(CID / 128, (NN + 127) / 128, NB);   // (4, 25, 8)
    gemm128<false, true, true><<<gProj, blk>>>(
        x1, NN, strideX, th_w, CC, 0, th, CID, strideP, NN, CID, CC, th_b);
    gemm128<false, true, true><<<gProj, blk>>>(
        x2, NN, strideX, ph_w, CC, 0, ph, CID, strideP, NN, CID, CC, ph_b);
    gemm128<false, true, true><<<gProj, blk>>>(
        x2, NN, strideX, g_w, CC, 0, gx, CID, strideP, NN, CID, CC, g_b);

    // scores: th @ ph^T  (both K contiguous)
    dim3 gScore((NN + 127) / 128, (NN + 127) / 128, NB);  // (25, 25, 8)
    gemm128<true, true, false><<<gScore, blk>>>(
        th, CID, strideP, ph, CID, strideP, f, NN, strideF, NN, NN, CID, nullptr);

    // softmax over last dim
    softmax_rows<<<ROWS_TOT, blk>>>(f);

    // y = attn @ gx
    dim3 gY(CID / 128, (NN + 127) / 128, NB);
    gemm128<true, false, false><<<gY, blk>>>(
        f, NN, strideF, gx, CID, strideP, y, CID, strideP, NN, CID, NN, nullptr);

    // wy = y @ wz^T + b
    dim3 gWY(CC / 128, (NN + 127) / 128, NB);
    gemm128<true, true, true><<<gWY, blk>>>(
        y, CID, strideP, wz_w, CID, 0, wy, CC, strideWY, NN, CC, CID, wz_b);

    // batchnorm stats (deterministic two-stage)
    bn_partial<<<dim3(CC / 256, BN_CHUNKS), blk>>>(wy);
    bn_finalize<<<dim3(CC / 256), blk>>>(gam, bet);

    // normalize + residual + transpose to NCHW
    out_kernel<<<dim3(NN / 32, CC / 32, NB), dim3(32, 8)>>>(wy, x1, out);
}

// round 7
// speedup vs baseline: 1.6557x; 1.6557x over previous
#include <cuda_runtime.h>
#include <cuda_bf16.h>
#include <cstdint>
#include <math.h>

// ---------------- problem constants ----------------
#define NB  8
#define CC  1024
#define CID 512
#define NN  3136
#define ROWS_TOT (NB * NN)
#define BN_CHUNKS 98

// ---------------- device scratch ----------------
static constexpr size_t P_X = (size_t)NB * NN * CC;    // x splits, per plane
static constexpr size_t P_P = (size_t)NB * NN * CID;   // th/ph/gT/y, per plane
static constexpr size_t P_W = (size_t)CID * CC;        // weights, per plane
static constexpr size_t P_F = (size_t)NB * NN * NN;    // scores / attn

__device__ __nv_bfloat16 g_xs1[2 * P_X];
__device__ __nv_bfloat16 g_xs2[2 * P_X];
__device__ __nv_bfloat16 g_thw[2 * P_W];
__device__ __nv_bfloat16 g_phw[2 * P_W];
__device__ __nv_bfloat16 g_gw [2 * P_W];
__device__ __nv_bfloat16 g_wzw[2 * P_W];
__device__ __nv_bfloat16 g_ths[2 * P_P];
__device__ __nv_bfloat16 g_phs[2 * P_P];
__device__ __nv_bfloat16 g_gTs[2 * P_P];
__device__ __nv_bfloat16 g_ys [2 * P_P];
__device__ float g_f[P_F];
__device__ __nv_bfloat16 g_as[2 * P_F];
__device__ float g_wy[(size_t)NB * NN * CC];
__device__ float g_part[BN_CHUNKS * CC * 2];
__device__ float g_ab[CC * 2];

// ---------------- hmma wrapper ----------------
__device__ __forceinline__ void mma_bf16(float* c, const uint32_t* a, const uint32_t* b)
{
    asm volatile(
        "mma.sync.aligned.m16n8k16.row.col.f32.bf16.bf16.f32 "
        "{%0,%1,%2,%3}, {%4,%5,%6,%7}, {%8,%9}, {%0,%1,%2,%3};"
        : "+f"(c[0]), "+f"(c[1]), "+f"(c[2]), "+f"(c[3])
        : "r"(a[0]), "r"(a[1]), "r"(a[2]), "r"(a[3]), "r"(b[0]), "r"(b[1]));
}

// smem: per stage, A tile 128 rows x 40 bf16 (32 used, 8 pad), B same.
#define ROW_PAD 40
#define A_ELEMS (128 * ROW_PAD)
#define STAGE_ELEMS (2 * A_ELEMS)
#define SMEM_BYTES (2 * STAGE_ELEMS * 2)   // 2 stages * elems * sizeof(bf16) = 40960

// =====================================================================
// HMMA GEMM: D(M x N) = sum over 3 split passes of A(M,K) * B(N,K)^T
//   pass 0: A.hi * B.hi   pass 1: A.hi * B.lo   pass 2: A.lo * B.hi
// A, B K-contiguous bf16 planes (lo plane at +planeA / +planeB).
// BIAS: 0 none, 1 col (bias[n]), 2 row (bias[m]).
// Output: fp32 (Cf != nullptr) or split bf16 (Chi/Clo).
// 128x128 tile per CTA, 256 threads, K-step 32, double-buffered.
// =====================================================================
template <int BIAS>
__global__ void __launch_bounds__(256, 2)
hm_gemm(const __nv_bfloat16* __restrict__ A, int lda, size_t batchA, size_t planeA,
        const __nv_bfloat16* __restrict__ B, int ldb, size_t batchB, size_t planeB,
        int M, int N, int K,
        const float* __restrict__ bias,
        float* __restrict__ Cf,
        __nv_bfloat16* __restrict__ Chi, __nv_bfloat16* __restrict__ Clo,
        int ldc, size_t batchC)
{
    extern __shared__ __nv_bfloat16 sm[];

    const int tid  = threadIdx.x;
    const int wid  = tid >> 5;
    const int lane = tid & 31;
    const int gid  = lane >> 2;       // 0..7
    const int tig  = lane & 3;        // 0..3
    const int warp_m = (wid & 1) * 64;
    const int warp_n = (wid >> 1) * 32;

    const int bz = blockIdx.z;
    const int n0 = blockIdx.x * 128;
    const int m0 = blockIdx.y * 128;

    const __nv_bfloat16* Ab = A + (size_t)bz * batchA;
    const __nv_bfloat16* Bb = B + (size_t)bz * batchB;

    // global tile loader mapping: each thread loads 32B (16 bf16) of A and B
    const int grow = tid >> 1;            // 0..127
    const int gcol = (tid & 1) * 16;      // element offset within 32-elem k-slab
    const bool mok = (m0 + grow) < M;
    const bool nok = (n0 + grow) < N;

    const int kPerPass = K >> 5;          // K/32
    const int nIter = 3 * kPerPass;

    float acc[4][4][4];
#pragma unroll
    for (int i = 0; i < 4; i++)
#pragma unroll
        for (int j = 0; j < 4; j++)
#pragma unroll
            for (int q = 0; q < 4; q++) acc[i][j][q] = 0.f;

    const uint4 zero4 = make_uint4(0, 0, 0, 0);
    uint4 va0, va1, vb0, vb1;

    // ---- load iteration 0 ----
    {
        const __nv_bfloat16* ap = Ab + (size_t)(m0 + grow) * lda + gcol;
        const __nv_bfloat16* bp = Bb + (size_t)(n0 + grow) * ldb + gcol;
        va0 = mok ? ((const uint4*)ap)[0] : zero4;
        va1 = mok ? ((const uint4*)ap)[1] : zero4;
        vb0 = nok ? ((const uint4*)bp)[0] : zero4;
        vb1 = nok ? ((const uint4*)bp)[1] : zero4;
        __nv_bfloat16* da = sm + grow * ROW_PAD + gcol;
        __nv_bfloat16* db = sm + A_ELEMS + grow * ROW_PAD + gcol;
        ((uint4*)da)[0] = va0; ((uint4*)da)[1] = va1;
        ((uint4*)db)[0] = vb0; ((uint4*)db)[1] = vb1;
    }
    __syncthreads();

    for (int it = 0; it < nIter; ++it) {
        // prefetch next tile into registers
        const bool more = (it + 1) < nIter;
        if (more) {
            const int itn = it + 1;
            const int p  = itn / kPerPass;
            const int kc = itn - p * kPerPass;
            const size_t offA = (p == 2) ? planeA : 0;
            const size_t offB = (p == 1) ? planeB : 0;
            const __nv_bfloat16* ap = Ab + offA + (size_t)(m0 + grow) * lda + kc * 32 + gcol;
            const __nv_bfloat16* bp = Bb + offB + (size_t)(n0 + grow) * ldb + kc * 32 + gcol;
            va0 = mok ? ((const uint4*)ap)[0] : zero4;
            va1 = mok ? ((const uint4*)ap)[1] : zero4;
            vb0 = nok ? ((const uint4*)bp)[0] : zero4;
            vb1 = nok ? ((const uint4*)bp)[1] : zero4;
        }

        // compute current stage
        const __nv_bfloat16* As = sm + (it & 1) * STAGE_ELEMS;
        const __nv_bfloat16* Bs = As + A_ELEMS;
#pragma unroll
        for (int ks = 0; ks < 2; ks++) {
            uint32_t bfr[4][2];
#pragma unroll
            for (int nf = 0; nf < 4; nf++) {
                const uint32_t* bp =
                    (const uint32_t*)(Bs + (warp_n + nf * 8 + gid) * ROW_PAD + ks * 16 + tig * 2);
                bfr[nf][0] = bp[0];
                bfr[nf][1] = bp[4];
            }
#pragma unroll
            for (int mf = 0; mf < 4; mf++) {
                uint32_t afr[4];
                const uint32_t* ap =
                    (const uint32_t*)(As + (warp_m + mf * 16 + gid) * ROW_PAD + ks * 16 + tig * 2);
                afr[0] = ap[0];
                afr[2] = ap[4];
                afr[1] = ap[8 * ROW_PAD / 2];
                afr[3] = ap[8 * ROW_PAD / 2 + 4];
#pragma unroll
                for (int nf = 0; nf < 4; nf++)
                    mma_bf16(acc[mf][nf], afr, bfr[nf]);
            }
        }

        // stage next tile
        if (more) {
            __nv_bfloat16* base = sm + ((it + 1) & 1) * STAGE_ELEMS;
            __nv_bfloat16* da = base + grow * ROW_PAD + gcol;
            __nv_bfloat16* db = base + A_ELEMS + grow * ROW_PAD + gcol;
            ((uint4*)da)[0] = va0; ((uint4*)da)[1] = va1;
            ((uint4*)db)[0] = vb0; ((uint4*)db)[1] = vb1;
        }
        __syncthreads();
    }

    // ---------------- epilogue: fragments -> gmem ----------------
    float* Cfb = Cf ? Cf + (size_t)bz * batchC : (float*)0;
    __nv_bfloat16* Chb = Chi ? Chi + (size_t)bz * batchC : (__nv_bfloat16*)0;
    __nv_bfloat16* Clb = Clo ? Clo + (size_t)bz * batchC : (__nv_bfloat16*)0;

#pragma unroll
    for (int mf = 0; mf < 4; mf++) {
#pragma unroll
        for (int nf = 0; nf < 4; nf++) {
            const int col = n0 + warp_n + nf * 8 + tig * 2;
            if (col >= N) continue;
            float bcol0 = 0.f, bcol1 = 0.f;
            if (BIAS == 1) { bcol0 = bias[col]; bcol1 = bias[col + 1]; }
#pragma unroll
            for (int half = 0; half < 2; half++) {
                const int row = m0 + warp_m + mf * 16 + gid + half * 8;
                if (row >= M) continue;
                float v0 = acc[mf][nf][half * 2 + 0];
                float v1 = acc[mf][nf][half * 2 + 1];
                if (BIAS == 1) { v0 += bcol0; v1 += bcol1; }
                if (BIAS == 2) { float br = bias[row]; v0 += br; v1 += br; }
                const size_t o = (size_t)row * ldc + col;
                if (Cfb) {
                    *(float2*)(Cfb + o) = make_float2(v0, v1);
                } else {
                    __nv_bfloat16 h0 = __float2bfloat16(v0);
                    __nv_bfloat16 h1 = __float2bfloat16(v1);
                    __nv_bfloat162 hh, ll;
                    hh.x = h0; hh.y = h1;
                    ll.x = __float2bfloat16(v0 - __bfloat162float(h0));
                    ll.y = __float2bfloat16(v1 - __bfloat162float(h1));
                    *(__nv_bfloat162*)(Chb + o) = hh;
                    *(__nv_bfloat162*)(Clb + o) = ll;
                }
            }
        }
    }
}

// =====================================================================
// NCHW -> NHWC transpose + bf16 hi/lo split of x1/x2
// =====================================================================
__global__ void __launch_bounds__(256)
split_tr(const float* __restrict__ x, __nv_bfloat16* __restrict__ hi,
         __nv_bfloat16* __restrict__ lo)
{
    __shared__ float t[32][33];
    const int b = blockIdx.z;
    const int n0 = blockIdx.x * 32;
    const int c0 = blockIdx.y * 32;
    const int tx = threadIdx.x, ty = threadIdx.y;

    for (int i = ty; i < 32; i += 8)
        t[i][tx] = x[((size_t)b * CC + c0 + i) * NN + n0 + tx];
    __syncthreads();
    for (int i = ty; i < 32; i += 8) {
        float v = t[tx][i];
        size_t o = ((size_t)b * NN + n0 + i) * CC + c0 + tx;
        __nv_bfloat16 h = __float2bfloat16(v);
        hi[o] = h;
        lo[o] = __float2bfloat16(v - __bfloat162float(h));
    }
}

// elementwise weight split
__global__ void __launch_bounds__(256)
split_w(const float* __restrict__ w, __nv_bfloat16* __restrict__ hi,
        __nv_bfloat16* __restrict__ lo, int n)
{
    int i = blockIdx.x * 256 + threadIdx.x;
    if (i < n) {
        float v = w[i];
        __nv_bfloat16 h = __float2bfloat16(v);
        hi[i] = h;
        lo[i] = __float2bfloat16(v - __bfloat162float(h));
    }
}

// =====================================================================
// Row softmax over NN, writes split bf16 attn
// =====================================================================
__global__ void __launch_bounds__(256)
softmax_split(const float* __restrict__ F, __nv_bfloat16* __restrict__ hi,
              __nv_bfloat16* __restrict__ lo)
{
    __shared__ float buf[NN];
    __shared__ float red[256];
    const size_t row = blockIdx.x;
    const float* __restrict__ p = F + row * (size_t)NN;
    const int t = threadIdx.x;

    float m = -3.402823466e38f;
    for (int i = t; i < NN; i += 256) {
        float v = p[i];
        buf[i] = v;
        m = fmaxf(m, v);
    }
    red[t] = m; __syncthreads();
    for (int s = 128; s > 0; s >>= 1) {
        if (t < s) red[t] = fmaxf(red[t], red[t + s]);
        __syncthreads();
    }
    m = red[0];
    __syncthreads();

    float sum = 0.f;
    for (int i = t; i < NN; i += 256) {
        float e = __expf(buf[i] - m);
        buf[i] = e;
        sum += e;
    }
    red[t] = sum; __syncthreads();
    for (int s = 128; s > 0; s >>= 1) {
        if (t < s) red[t] += red[t + s];
        __syncthreads();
    }
    float inv = 1.f / red[0];
    for (int i = t; i < NN; i += 256) {
        float v = buf[i] * inv;
        __nv_bfloat16 h = __float2bfloat16(v);
        hi[row * NN + i] = h;
        lo[row * NN + i] = __float2bfloat16(v - __bfloat162float(h));
    }
}

// =====================================================================
// BatchNorm stats (deterministic two-stage)
// =====================================================================
__global__ void __launch_bounds__(256)
bn_partial(const float* __restrict__ wy)
{
    int c = blockIdx.x * 256 + threadIdx.x;
    int chunk = blockIdx.y;
    int r0 = chunk * 256;
    float s = 0.f, s2 = 0.f;
    for (int r = r0; r < r0 + 256; r++) {
        float v = wy[(size_t)r * CC + c];
        s += v; s2 += v * v;
    }
    g_part[((size_t)chunk * CC + c) * 2 + 0] = s;
    g_part[((size_t)chunk * CC + c) * 2 + 1] = s2;
}

__global__ void __launch_bounds__(256)
bn_finalize(const float* __restrict__ gamma, const float* __restrict__ beta)
{
    int c = blockIdx.x * 256 + threadIdx.x;
    float s = 0.f, s2 = 0.f;
    for (int ch = 0; ch < BN_CHUNKS; ch++) {
        s  += g_part[((size_t)ch * CC + c) * 2 + 0];
        s2 += g_part[((size_t)ch * CC + c) * 2 + 1];
    }
    const float invR = 1.f / (float)ROWS_TOT;
    float mu  = s * invR;
    float var = s2 * invR - mu * mu;
    float a = gamma[c] * rsqrtf(var + 1e-5f);
    g_ab[c * 2 + 0] = a;
    g_ab[c * 2 + 1] = beta[c] - mu * a;
}

// =====================================================================
// normalize + residual + NHWC->NCHW transpose
// =====================================================================
__global__ void __launch_bounds__(256)
out_kernel(const float* __restrict__ wy, const float* __restrict__ x1,
           float* __restrict__ out)
{
    __shared__ float tile[32][33];
    int b  = blockIdx.z;
    int n0 = blockIdx.x * 32;
    int c0 = blockIdx.y * 32;
    int tx = threadIdx.x, ty = threadIdx.y;

    for (int i = ty; i < 32; i += 8) {
        int c = c0 + tx, n = n0 + i;
        float v = wy[((size_t)b * NN + n) * CC + c];
        tile[i][tx] = v * g_ab[c * 2 + 0] + g_ab[c * 2 + 1];
    }
    __syncthreads();
    for (int i = ty; i < 32; i += 8) {
        int c = c0 + i, n = n0 + tx;
        size_t idx = ((size_t)b * CC + c) * (size_t)NN + n;
        out[idx] = tile[tx][i] + x1[idx];
    }
}

// =====================================================================
// launcher
// =====================================================================
extern "C" void kernel_launch(void* const* d_in, const int* in_sizes, int n_in,
                              void* d_out, int out_size)
{
    const float* x1   = (const float*)d_in[0];
    const float* x2   = (const float*)d_in[1];
    const float* g_w  = (const float*)d_in[2];
    const float* g_b  = (const float*)d_in[3];
    const float* th_w = (const float*)d_in[4];
    const float* th_b = (const float*)d_in[5];
    const float* ph_w = (const float*)d_in[6];
    const float* ph_b = (const float*)d_in[7];
    const float* wz_w = (const float*)d_in[8];
    const float* wz_b = (const float*)d_in[9];
    const float* gam  = (const float*)d_in[10];
    const float* bet  = (const float*)d_in[11];
    float* out = (float*)d_out;

    __nv_bfloat16 *xs1, *xs2, *thw, *phw, *gw, *wzw, *ths, *phs, *gTs, *ys, *as;
    float *f, *wy;
    cudaGetSymbolAddress((void**)&xs1, g_xs1);
    cudaGetSymbolAddress((void**)&xs2, g_xs2);
    cudaGetSymbolAddress((void**)&thw, g_thw);
    cudaGetSymbolAddress((void**)&phw, g_phw);
    cudaGetSymbolAddress((void**)&gw,  g_gw);
    cudaGetSymbolAddress((void**)&wzw, g_wzw);
    cudaGetSymbolAddress((void**)&ths, g_ths);
    cudaGetSymbolAddress((void**)&phs, g_phs);
    cudaGetSymbolAddress((void**)&gTs, g_gTs);
    cudaGetSymbolAddress((void**)&ys,  g_ys);
    cudaGetSymbolAddress((void**)&as,  g_as);
    cudaGetSymbolAddress((void**)&f,   g_f);
    cudaGetSymbolAddress((void**)&wy,  g_wy);

    dim3 blk256(256);
    dim3 blkT(32, 8);

    // 1) input transpose + split, weight splits
    split_tr<<<dim3(NN / 32, CC / 32, NB), blkT>>>(x1, xs1, xs1 + P_X);
    split_tr<<<dim3(NN / 32, CC / 32, NB), blkT>>>(x2, xs2, xs2 + P_X);
    split_w<<<(int)((P_W + 255) / 256), blk256>>>(th_w, thw, thw + P_W, (int)P_W);
    split_w<<<(int)((P_W + 255) / 256), blk256>>>(ph_w, phw, phw + P_W, (int)P_W);
    split_w<<<(int)((P_W + 255) / 256), blk256>>>(g_w,  gw,  gw  + P_W, (int)P_W);
    split_w<<<(int)((P_W + 255) / 256), blk256>>>(wz_w, wzw, wzw + P_W, (int)P_W);

    const size_t bX = (size_t)NN * CC;    // per-batch x split
    const size_t bP = (size_t)NN * CID;   // per-batch th/ph/gT/y
    const size_t bF = (size_t)NN * NN;

    const int mt = (NN + 127) / 128;      // 25 tiles over 3136

    // 2) th = x1f @ th_w^T + th_b   -> split (B,N,CID)
    hm_gemm<1><<<dim3(CID / 128, mt, NB), 256, SMEM_BYTES>>>(
        xs1, CC, bX, P_X, thw, CC, 0, P_W,
        NN, CID, CC, th_b, nullptr, ths, ths + P_P, CID, bP);
    // 3) ph = x2f @ ph_w^T + ph_b
    hm_gemm<1><<<dim3(CID / 128, mt, NB), 256, SMEM_BYTES>>>(
        xs2, CC, bX, P_X, phw, CC, 0, P_W,
        NN, CID, CC, ph_b, nullptr, phs, phs + P_P, CID, bP);
    // 4) gT[d,n] = sum_c g_w[d,c] x2f[n,c] + g_b[d]  -> split (B,CID,N), row bias
    hm_gemm<2><<<dim3(mt, CID / 128, NB), 256, SMEM_BYTES>>>(
        gw, CC, 0, P_W, xs2, CC, bX, P_X,
        CID, NN, CC, g_b, nullptr, gTs, gTs + P_P, NN, bP);
    // 5) f = th @ ph^T   -> fp32 (B,N,N)
    hm_gemm<0><<<dim3(mt, mt, NB), 256, SMEM_BYTES>>>(
        ths, CID, bP, P_P, phs, CID, bP, P_P,
        NN, NN, CID, nullptr, f, nullptr, nullptr, NN, bF);
    // 6) softmax -> split attn
    softmax_split<<<ROWS_TOT, blk256>>>(f, as, as + P_F);
    // 7) y[n,d] = sum_m attn[n,m] gT[d,m]  -> split (B,N,CID)
    hm_gemm<0><<<dim3(CID / 128, mt, NB), 256, SMEM_BYTES>>>(
        as, NN, bF, P_F, gTs, NN, bP, P_P,
        NN, CID, NN, nullptr, nullptr, ys, ys + P_P, CID, bP);
    // 8) wy = y @ wz_w^T + wz_b  -> fp32 (B,N,C)
    hm_gemm<1><<<dim3(CC / 128, mt, NB), 256, SMEM_BYTES>>>(
        ys, CID, bP, P_P, wzw, CID, 0, P_W,
        NN, CC, CID, wz_b, wy, nullptr, nullptr, CC, (size_t)NN * CC);

    // 9) BN stats + output
    bn_partial<<<dim3(CC / 256, BN_CHUNKS), blk256>>>(wy);
    bn_finalize<<<dim3(CC / 256), blk256>>>(gam, bet);
    out_kernel<<<dim3(NN / 32, CC / 32, NB), blkT>>>(wy, x1, out);
}

// round 8
// speedup vs baseline: 2.8312x; 1.7100x over previous
#include <cuda_runtime.h>
#include <cuda_bf16.h>
#include <cstdint>
#include <math.h>

// ---------------- problem constants ----------------
#define NB  8
#define CC  1024
#define CID 512
#define NN  3136
#define ROWS_TOT (NB * NN)
#define BN_CHUNKS 98

// ---------------- device scratch ----------------
static constexpr size_t P_X = (size_t)NB * NN * CC;    // x splits, per plane
static constexpr size_t P_P = (size_t)NB * NN * CID;   // th/ph/gT/y, per plane
static constexpr size_t P_W = (size_t)CID * CC;        // weights, per plane
static constexpr size_t P_F = (size_t)NB * NN * NN;    // scores / attn

__device__ __nv_bfloat16 g_xs1[2 * P_X];
__device__ __nv_bfloat16 g_xs2[2 * P_X];
__device__ __nv_bfloat16 g_thw[2 * P_W];
__device__ __nv_bfloat16 g_phw[2 * P_W];
__device__ __nv_bfloat16 g_gw [2 * P_W];
__device__ __nv_bfloat16 g_wzw[2 * P_W];
__device__ __nv_bfloat16 g_ths[2 * P_P];
__device__ __nv_bfloat16 g_phs[2 * P_P];
__device__ __nv_bfloat16 g_gTs[2 * P_P];
__device__ __nv_bfloat16 g_ys [2 * P_P];
__device__ float g_f[P_F];
__device__ __nv_bfloat16 g_as[2 * P_F];
__device__ float g_wy[(size_t)NB * NN * CC];
__device__ float g_part[BN_CHUNKS * CC * 2];
__device__ float g_ab[CC * 2];

// ---------------- mma / ldmatrix / cp.async wrappers ----------------
__device__ __forceinline__ void mma_bf16(float* c, const uint32_t* a,
                                         uint32_t b0, uint32_t b1)
{
    asm volatile(
        "mma.sync.aligned.m16n8k16.row.col.f32.bf16.bf16.f32 "
        "{%0,%1,%2,%3}, {%4,%5,%6,%7}, {%8,%9}, {%0,%1,%2,%3};"
        : "+f"(c[0]), "+f"(c[1]), "+f"(c[2]), "+f"(c[3])
        : "r"(a[0]), "r"(a[1]), "r"(a[2]), "r"(a[3]), "r"(b0), "r"(b1));
}

#define LDSM_X4(r, addr) \
    asm volatile("ldmatrix.sync.aligned.m8n8.x4.shared.b16 {%0,%1,%2,%3}, [%4];" \
        : "=r"((r)[0]), "=r"((r)[1]), "=r"((r)[2]), "=r"((r)[3]) : "r"(addr))

__device__ __forceinline__ void cp16(uint32_t dst, const void* src, int srcsize)
{
    asm volatile("cp.async.cg.shared.global [%0], [%1], 16, %2;"
        :: "r"(dst), "l"(src), "r"(srcsize));
}
#define CP_COMMIT() asm volatile("cp.async.commit_group;" ::: "memory")
#define CP_WAIT(n)  asm volatile("cp.async.wait_group %0;" :: "n"(n) : "memory")

// ---------------- GEMM tiling constants ----------------
#define STAGES 4
#define ROW_PAD 40                       // bf16 elems per smem row (32 + 8 pad)
#define ROW_BYTES 80
#define A_BYTES (128 * ROW_BYTES)        // 10240 per stage
#define STAGE_BYTES (2 * A_BYTES)        // A + B = 20480
#define SMEM_BYTES (STAGES * STAGE_BYTES) // 81920

// =====================================================================
// HMMA GEMM: D(M x N) = sum over 3 split passes of A(M,K) * B(N,K)^T
//   pass 0: A.hi*B.hi   pass 1: A.hi*B.lo   pass 2: A.lo*B.hi
// A, B K-contiguous bf16 planes (lo plane at +planeA / +planeB).
// BIAS: 0 none, 1 col (bias[n]), 2 row (bias[m]).
// Output: fp32 (Cf != nullptr) or split bf16 (Chi/Clo).
// 128x128 tile per CTA, 256 threads, K-step 32, cp.async 4-stage, ldmatrix.
// =====================================================================
template <int BIAS>
__global__ void __launch_bounds__(256, 2)
hm_gemm(const __nv_bfloat16* __restrict__ A, int lda, size_t batchA, size_t planeA,
        const __nv_bfloat16* __restrict__ B, int ldb, size_t batchB, size_t planeB,
        int M, int N, int K,
        const float* __restrict__ bias,
        float* __restrict__ Cf,
        __nv_bfloat16* __restrict__ Chi, __nv_bfloat16* __restrict__ Clo,
        int ldc, size_t batchC)
{
    extern __shared__ __align__(16) uint8_t smraw[];
    const uint32_t smBase = (uint32_t)__cvta_generic_to_shared(smraw);

    const int tid  = threadIdx.x;
    const int wid  = tid >> 5;
    const int lane = tid & 31;
    const int gid  = lane >> 2;
    const int tig  = lane & 3;
    const int warp_m = (wid & 1) * 64;
    const int warp_n = (wid >> 1) * 32;

    const int bz = blockIdx.z;
    const int n0 = blockIdx.x * 128;
    const int m0 = blockIdx.y * 128;

    const __nv_bfloat16* Ab = A + (size_t)bz * batchA;
    const __nv_bfloat16* Bb = B + (size_t)bz * batchB;

    // cp.async loader mapping: thread -> (row, 32B half of the 64B k-slab)
    const int lrow = tid >> 1;
    const int lcol = (tid & 1) * 32;            // byte offset within row slab
    const int aok = ((m0 + lrow) < M) ? 16 : 0; // src-size (0 => zero-fill)
    const int bok = ((n0 + lrow) < N) ? 16 : 0;
    const char* aRow = (const char*)(Ab + (size_t)(m0 + lrow) * lda);
    const char* bRow = (const char*)(Bb + (size_t)(n0 + lrow) * ldb);
    const uint32_t sA = lrow * ROW_BYTES + lcol;
    const uint32_t sB = A_BYTES + lrow * ROW_BYTES + lcol;

    const int kPerPass = K >> 5;
    const int nIter = 3 * kPerPass;
    const size_t planeA2 = planeA * 2;          // byte offsets
    const size_t planeB2 = planeB * 2;

    // ldmatrix per-lane offsets (within a stage)
    const uint32_t aOff = (uint32_t)((warp_m + (lane & 15)) * ROW_BYTES + (lane >> 4) * 16);
    const uint32_t bOff = (uint32_t)(A_BYTES + (warp_n + (lane & 15)) * ROW_BYTES + (lane >> 4) * 16);

    float acc[4][4][4];
#pragma unroll
    for (int i = 0; i < 4; i++)
#pragma unroll
        for (int j = 0; j < 4; j++)
#pragma unroll
            for (int q = 0; q < 4; q++) acc[i][j][q] = 0.f;

    auto issue_stage = [&](int idx) {
        const int p  = idx / kPerPass;
        const int kc = idx - p * kPerPass;
        const size_t offA = (p == 2) ? planeA2 : 0;
        const size_t offB = (p == 1) ? planeB2 : 0;
        const uint32_t st = smBase + (uint32_t)(idx % STAGES) * STAGE_BYTES;
        const char* ga = aRow + offA + kc * 64 + lcol;
        const char* gb = bRow + offB + kc * 64 + lcol;
        cp16(st + sA,      ga,      aok);
        cp16(st + sA + 16, ga + 16, aok);
        cp16(st + sB,      gb,      bok);
        cp16(st + sB + 16, gb + 16, bok);
        CP_COMMIT();
    };

    // prologue
#pragma unroll
    for (int s = 0; s < STAGES - 1; s++) issue_stage(s);

    for (int it = 0; it < nIter; ++it) {
        if (it + STAGES - 1 < nIter) issue_stage(it + STAGES - 1);
        else CP_COMMIT();                        // empty group keeps count math simple
        CP_WAIT(STAGES - 2);
        __syncthreads();

        const uint32_t st = smBase + (uint32_t)(it % STAGES) * STAGE_BYTES;
#pragma unroll
        for (int ks = 0; ks < 2; ks++) {
            uint32_t bp0[4], bp1[4];
            LDSM_X4(bp0, st + bOff + ks * 32);
            LDSM_X4(bp1, st + bOff + 1280 + ks * 32);   // +16 n-rows
#pragma unroll
            for (int mf = 0; mf < 4; mf++) {
                uint32_t a[4];
                LDSM_X4(a, st + aOff + mf * 1280 + ks * 32);
                mma_bf16(acc[mf][0], a, bp0[0], bp0[2]);
                mma_bf16(acc[mf][1], a, bp0[1], bp0[3]);
                mma_bf16(acc[mf][2], a, bp1[0], bp1[2]);
                mma_bf16(acc[mf][3], a, bp1[1], bp1[3]);
            }
        }
        __syncthreads();                          // buffer it%STAGES reused next issue
    }

    // ---------------- epilogue: fragments -> gmem ----------------
    float* Cfb = Cf ? Cf + (size_t)bz * batchC : (float*)0;
    __nv_bfloat16* Chb = Chi ? Chi + (size_t)bz * batchC : (__nv_bfloat16*)0;
    __nv_bfloat16* Clb = Clo ? Clo + (size_t)bz * batchC : (__nv_bfloat16*)0;

#pragma unroll
    for (int mf = 0; mf < 4; mf++) {
#pragma unroll
        for (int nf = 0; nf < 4; nf++) {
            const int col = n0 + warp_n + nf * 8 + tig * 2;
            if (col >= N) continue;
            float bcol0 = 0.f, bcol1 = 0.f;
            if (BIAS == 1) { bcol0 = bias[col]; bcol1 = bias[col + 1]; }
#pragma unroll
            for (int half = 0; half < 2; half++) {
                const int row = m0 + warp_m + mf * 16 + gid + half * 8;
                if (row >= M) continue;
                float v0 = acc[mf][nf][half * 2 + 0];
                float v1 = acc[mf][nf][half * 2 + 1];
                if (BIAS == 1) { v0 += bcol0; v1 += bcol1; }
                if (BIAS == 2) { float br = bias[row]; v0 += br; v1 += br; }
                const size_t o = (size_t)row * ldc + col;
                if (Cfb) {
                    *(float2*)(Cfb + o) = make_float2(v0, v1);
                } else {
                    __nv_bfloat16 h0 = __float2bfloat16(v0);
                    __nv_bfloat16 h1 = __float2bfloat16(v1);
                    __nv_bfloat162 hh, ll;
                    hh.x = h0; hh.y = h1;
                    ll.x = __float2bfloat16(v0 - __bfloat162float(h0));
                    ll.y = __float2bfloat16(v1 - __bfloat162float(h1));
                    *(__nv_bfloat162*)(Chb + o) = hh;
                    *(__nv_bfloat162*)(Clb + o) = ll;
                }
            }
        }
    }
}

// =====================================================================
// NCHW -> NHWC transpose + bf16 hi/lo split of x1/x2
// =====================================================================
__global__ void __launch_bounds__(256)
split_tr(const float* __restrict__ x, __nv_bfloat16* __restrict__ hi,
         __nv_bfloat16* __restrict__ lo)
{
    __shared__ float t[32][33];
    const int b = blockIdx.z;
    const int n0 = blockIdx.x * 32;
    const int c0 = blockIdx.y * 32;
    const int tx = threadIdx.x, ty = threadIdx.y;

    for (int i = ty; i < 32; i += 8)
        t[i][tx] = x[((size_t)b * CC + c0 + i) * NN + n0 + tx];
    __syncthreads();
    for (int i = ty; i < 32; i += 8) {
        float v = t[tx][i];
        size_t o = ((size_t)b * NN + n0 + i) * CC + c0 + tx;
        __nv_bfloat16 h = __float2bfloat16(v);
        hi[o] = h;
        lo[o] = __float2bfloat16(v - __bfloat162float(h));
    }
}

// elementwise weight split
__global__ void __launch_bounds__(256)
split_w(const float* __restrict__ w, __nv_bfloat16* __restrict__ hi,
        __nv_bfloat16* __restrict__ lo, int n)
{
    int i = blockIdx.x * 256 + threadIdx.x;
    if (i < n) {
        float v = w[i];
        __nv_bfloat16 h = __float2bfloat16(v);
        hi[i] = h;
        lo[i] = __float2bfloat16(v - __bfloat162float(h));
    }
}

// =====================================================================
// Row softmax over NN, writes split bf16 attn
// =====================================================================
__global__ void __launch_bounds__(256)
softmax_split(const float* __restrict__ F, __nv_bfloat16* __restrict__ hi,
              __nv_bfloat16* __restrict__ lo)
{
    __shared__ float buf[NN];
    __shared__ float red[256];
    const size_t row = blockIdx.x;
    const float* __restrict__ p = F + row * (size_t)NN;
    const int t = threadIdx.x;

    float m = -3.402823466e38f;
    for (int i = t; i < NN; i += 256) {
        float v = p[i];
        buf[i] = v;
        m = fmaxf(m, v);
    }
    red[t] = m; __syncthreads();
    for (int s = 128; s > 0; s >>= 1) {
        if (t < s) red[t] = fmaxf(red[t], red[t + s]);
        __syncthreads();
    }
    m = red[0];
    __syncthreads();

    float sum = 0.f;
    for (int i = t; i < NN; i += 256) {
        float e = __expf(buf[i] - m);
        buf[i] = e;
        sum += e;
    }
    red[t] = sum; __syncthreads();
    for (int s = 128; s > 0; s >>= 1) {
        if (t < s) red[t] += red[t + s];
        __syncthreads();
    }
    float inv = 1.f / red[0];
    for (int i = t; i < NN; i += 256) {
        float v = buf[i] * inv;
        __nv_bfloat16 h = __float2bfloat16(v);
        hi[row * NN + i] = h;
        lo[row * NN + i] = __float2bfloat16(v - __bfloat162float(h));
    }
}

// =====================================================================
// BatchNorm stats (deterministic two-stage)
// =====================================================================
__global__ void __launch_bounds__(256)
bn_partial(const float* __restrict__ wy)
{
    int c = blockIdx.x * 256 + threadIdx.x;
    int chunk = blockIdx.y;
    int r0 = chunk * 256;
    float s = 0.f, s2 = 0.f;
    for (int r = r0; r < r0 + 256; r++) {
        float v = wy[(size_t)r * CC + c];
        s += v; s2 += v * v;
    }
    g_part[((size_t)chunk * CC + c) * 2 + 0] = s;
    g_part[((size_t)chunk * CC + c) * 2 + 1] = s2;
}

__global__ void __launch_bounds__(256)
bn_finalize(const float* __restrict__ gamma, const float* __restrict__ beta)
{
    int c = blockIdx.x * 256 + threadIdx.x;
    float s = 0.f, s2 = 0.f;
    for (int ch = 0; ch < BN_CHUNKS; ch++) {
        s  += g_part[((size_t)ch * CC + c) * 2 + 0];
        s2 += g_part[((size_t)ch * CC + c) * 2 + 1];
    }
    const float invR = 1.f / (float)ROWS_TOT;
    float mu  = s * invR;
    float var = s2 * invR - mu * mu;
    float a = gamma[c] * rsqrtf(var + 1e-5f);
    g_ab[c * 2 + 0] = a;
    g_ab[c * 2 + 1] = beta[c] - mu * a;
}

// =====================================================================
// normalize + residual + NHWC->NCHW transpose
// =====================================================================
__global__ void __launch_bounds__(256)
out_kernel(const float* __restrict__ wy, const float* __restrict__ x1,
           float* __restrict__ out)
{
    __shared__ float tile[32][33];
    int b  = blockIdx.z;
    int n0 = blockIdx.x * 32;
    int c0 = blockIdx.y * 32;
    int tx = threadIdx.x, ty = threadIdx.y;

    for (int i = ty; i < 32; i += 8) {
        int c = c0 + tx, n = n0 + i;
        float v = wy[((size_t)b * NN + n) * CC + c];
        tile[i][tx] = v * g_ab[c * 2 + 0] + g_ab[c * 2 + 1];
    }
    __syncthreads();
    for (int i = ty; i < 32; i += 8) {
        int c = c0 + i, n = n0 + tx;
        size_t idx = ((size_t)b * CC + c) * (size_t)NN + n;
        out[idx] = tile[tx][i] + x1[idx];
    }
}

// =====================================================================
// launcher
// =====================================================================
extern "C" void kernel_launch(void* const* d_in, const int* in_sizes, int n_in,
                              void* d_out, int out_size)
{
    const float* x1   = (const float*)d_in[0];
    const float* x2   = (const float*)d_in[1];
    const float* g_w  = (const float*)d_in[2];
    const float* g_b  = (const float*)d_in[3];
    const float* th_w = (const float*)d_in[4];
    const float* th_b = (const float*)d_in[5];
    const float* ph_w = (const float*)d_in[6];
    const float* ph_b = (const float*)d_in[7];
    const float* wz_w = (const float*)d_in[8];
    const float* wz_b = (const float*)d_in[9];
    const float* gam  = (const float*)d_in[10];
    const float* bet  = (const float*)d_in[11];
    float* out = (float*)d_out;

    // allow > 48KB dynamic smem (idempotent; not a stream operation)
    cudaFuncSetAttribute((const void*)hm_gemm<0>,
                         cudaFuncAttributeMaxDynamicSharedMemorySize, SMEM_BYTES);
    cudaFuncSetAttribute((const void*)hm_gemm<1>,
                         cudaFuncAttributeMaxDynamicSharedMemorySize, SMEM_BYTES);
    cudaFuncSetAttribute((const void*)hm_gemm<2>,
                         cudaFuncAttributeMaxDynamicSharedMemorySize, SMEM_BYTES);

    __nv_bfloat16 *xs1, *xs2, *thw, *phw, *gw, *wzw, *ths, *phs, *gTs, *ys, *as;
    float *f, *wy;
    cudaGetSymbolAddress((void**)&xs1, g_xs1);
    cudaGetSymbolAddress((void**)&xs2, g_xs2);
    cudaGetSymbolAddress((void**)&thw, g_thw);
    cudaGetSymbolAddress((void**)&phw, g_phw);
    cudaGetSymbolAddress((void**)&gw,  g_gw);
    cudaGetSymbolAddress((void**)&wzw, g_wzw);
    cudaGetSymbolAddress((void**)&ths, g_ths);
    cudaGetSymbolAddress((void**)&phs, g_phs);
    cudaGetSymbolAddress((void**)&gTs, g_gTs);
    cudaGetSymbolAddress((void**)&ys,  g_ys);
    cudaGetSymbolAddress((void**)&as,  g_as);
    cudaGetSymbolAddress((void**)&f,   g_f);
    cudaGetSymbolAddress((void**)&wy,  g_wy);

    dim3 blk256(256);
    dim3 blkT(32, 8);

    // 1) input transpose + split, weight splits
    split_tr<<<dim3(NN / 32, CC / 32, NB), blkT>>>(x1, xs1, xs1 + P_X);
    split_tr<<<dim3(NN / 32, CC / 32, NB), blkT>>>(x2, xs2, xs2 + P_X);
    split_w<<<(int)((P_W + 255) / 256), blk256>>>(th_w, thw, thw + P_W, (int)P_W);
    split_w<<<(int)((P_W + 255) / 256), blk256>>>(ph_w, phw, phw + P_W, (int)P_W);
    split_w<<<(int)((P_W + 255) / 256), blk256>>>(g_w,  gw,  gw  + P_W, (int)P_W);
    split_w<<<(int)((P_W + 255) / 256), blk256>>>(wz_w, wzw, wzw + P_W, (int)P_W);

    const size_t bX = (size_t)NN * CC;
    const size_t bP = (size_t)NN * CID;
    const size_t bF = (size_t)NN * NN;
    const int mt = (NN + 127) / 128;      // 25

    // 2) th = x1f @ th_w^T + th_b   -> split (B,N,CID)
    hm_gemm<1><<<dim3(CID / 128, mt, NB), 256, SMEM_BYTES>>>(
        xs1, CC, bX, P_X, thw, CC, 0, P_W,
        NN, CID, CC, th_b, nullptr, ths, ths + P_P, CID, bP);
    // 3) ph = x2f @ ph_w^T + ph_b
    hm_gemm<1><<<dim3(CID / 128, mt, NB), 256, SMEM_BYTES>>>(
        xs2, CC, bX, P_X, phw, CC, 0, P_W,
        NN, CID, CC, ph_b, nullptr, phs, phs + P_P, CID, bP);
    // 4) gT[d,n] = sum_c g_w[d,c] x2f[n,c] + g_b[d]  -> split (B,CID,N), row bias
    hm_gemm<2><<<dim3(mt, CID / 128, NB), 256, SMEM_BYTES>>>(
        gw, CC, 0, P_W, xs2, CC, bX, P_X,
        CID, NN, CC, g_b, nullptr, gTs, gTs + P_P, NN, bP);
    // 5) f = th @ ph^T   -> fp32 (B,N,N)
    hm_gemm<0><<<dim3(mt, mt, NB), 256, SMEM_BYTES>>>(
        ths, CID, bP, P_P, phs, CID, bP, P_P,
        NN, NN, CID, nullptr, f, nullptr, nullptr, NN, bF);
    // 6) softmax -> split attn
    softmax_split<<<ROWS_TOT, blk256>>>(f, as, as + P_F);
    // 7) y[n,d] = sum_m attn[n,m] gT[d,m]  -> split (B,N,CID)
    hm_gemm<0><<<dim3(CID / 128, mt, NB), 256, SMEM_BYTES>>>(
        as, NN, bF, P_F, gTs, NN, bP, P_P,
        NN, CID, NN, nullptr, nullptr, ys, ys + P_P, CID, bP);
    // 8) wy = y @ wz_w^T + wz_b  -> fp32 (B,N,C)
    hm_gemm<1><<<dim3(CC / 128, mt, NB), 256, SMEM_BYTES>>>(
        ys, CID, bP, P_P, wzw, CID, 0, P_W,
        NN, CC, CID, wz_b, wy, nullptr, nullptr, CC, (size_t)NN * CC);

    // 9) BN stats + output
    bn_partial<<<dim3(CC / 256, BN_CHUNKS), blk256>>>(wy);
    bn_finalize<<<dim3(CC / 256), blk256>>>(gam, bet);
    out_kernel<<<dim3(NN / 32, CC / 32, NB), blkT>>>(wy, x1, out);
}

// round 9
// speedup vs baseline: 3.0055x; 1.0616x over previous
#include <cuda_runtime.h>
#include <cuda_bf16.h>
#include <cstdint>
#include <math.h>

// ---------------- problem constants ----------------
#define NB  8
#define CC  1024
#define CID 512
#define NN  3136
#define ROWS_TOT (NB * NN)
#define NTILE_M 25                 // ceil(3136/128)
#define BN_CHUNKS (NB * NTILE_M)   // 200

// ---------------- device scratch ----------------
static constexpr size_t P_X = (size_t)NB * NN * CC;
static constexpr size_t P_P = (size_t)NB * NN * CID;
static constexpr size_t P_W = (size_t)CID * CC;
static constexpr size_t P_F = (size_t)NB * NN * NN;

__device__ __nv_bfloat16 g_xs1[2 * P_X];
__device__ __nv_bfloat16 g_xs2[2 * P_X];
__device__ __nv_bfloat16 g_thw[2 * P_W];
__device__ __nv_bfloat16 g_phw[2 * P_W];
__device__ __nv_bfloat16 g_gw [2 * P_W];
__device__ __nv_bfloat16 g_wzw[2 * P_W];
__device__ __nv_bfloat16 g_ths[2 * P_P];
__device__ __nv_bfloat16 g_phs[2 * P_P];
__device__ __nv_bfloat16 g_gTs[2 * P_P];
__device__ __nv_bfloat16 g_ys [2 * P_P];
__device__ float g_f[P_F];
__device__ __nv_bfloat16 g_as[2 * P_F];
__device__ float g_wy[(size_t)NB * NN * CC];
__device__ float g_part[(size_t)BN_CHUNKS * CC * 2];
__device__ float g_ab[CC * 2];

// ---------------- mma / ldmatrix / cp.async wrappers ----------------
__device__ __forceinline__ void mma_bf16(float* c, const uint32_t* a,
                                         uint32_t b0, uint32_t b1)
{
    asm volatile(
        "mma.sync.aligned.m16n8k16.row.col.f32.bf16.bf16.f32 "
        "{%0,%1,%2,%3}, {%4,%5,%6,%7}, {%8,%9}, {%0,%1,%2,%3};"
        : "+f"(c[0]), "+f"(c[1]), "+f"(c[2]), "+f"(c[3])
        : "r"(a[0]), "r"(a[1]), "r"(a[2]), "r"(a[3]), "r"(b0), "r"(b1));
}

#define LDSM_X4(r, addr) \
    asm volatile("ldmatrix.sync.aligned.m8n8.x4.shared.b16 {%0,%1,%2,%3}, [%4];" \
        : "=r"((r)[0]), "=r"((r)[1]), "=r"((r)[2]), "=r"((r)[3]) : "r"(addr))

__device__ __forceinline__ void cp16(uint32_t dst, const void* src, int srcsize)
{
    asm volatile("cp.async.cg.shared.global [%0], [%1], 16, %2;"
        :: "r"(dst), "l"(src), "r"(srcsize));
}
#define CP_COMMIT() asm volatile("cp.async.commit_group;" ::: "memory")
#define CP_WAIT(n)  asm volatile("cp.async.wait_group %0;" :: "n"(n) : "memory")

// ---------------- GEMM tiling constants ----------------
#define STAGES 4
#define ROW_BYTES 80
#define A_BYTES (128 * ROW_BYTES)
#define STAGE_BYTES (2 * A_BYTES)
#define SMEM_BYTES (STAGES * STAGE_BYTES)   // 81920

// =====================================================================
// GEMM body: D(M x N) = 3-pass split-bf16 A(M,K) * B(N,K)^T
//   pass 0: A.hi*B.hi   pass 1: A.hi*B.lo   pass 2: A.lo*B.hi
// BIAS: 0 none, 1 col, 2 row.  BN: accumulate column (sum,sumsq) partials.
// =====================================================================
template <int BIAS, bool BN>
__device__ __forceinline__ void gemm_body(
    uint8_t* smraw,
    const __nv_bfloat16* __restrict__ A, int lda, size_t planeA2,
    const __nv_bfloat16* __restrict__ B, int ldb, size_t planeB2,
    int M, int N, int K,
    const float* __restrict__ bias,
    float* __restrict__ Cfb,
    __nv_bfloat16* __restrict__ Chb, __nv_bfloat16* __restrict__ Clb,
    int ldc, int m0, int n0, float* __restrict__ bnPart)
{
    const uint32_t smBase = (uint32_t)__cvta_generic_to_shared(smraw);
    const int tid  = threadIdx.x;
    const int wid  = tid >> 5;
    const int lane = tid & 31;
    const int gid  = lane >> 2;
    const int tig  = lane & 3;
    const int warp_m = (wid & 1) * 64;
    const int warp_n = (wid >> 1) * 32;

    const int lrow = tid >> 1;
    const int lcol = (tid & 1) * 32;
    const int aok = ((m0 + lrow) < M) ? 16 : 0;
    const int bok = ((n0 + lrow) < N) ? 16 : 0;
    const char* aRow = (const char*)(A + (size_t)(m0 + lrow) * lda);
    const char* bRow = (const char*)(B + (size_t)(n0 + lrow) * ldb);
    const uint32_t sA = lrow * ROW_BYTES + lcol;
    const uint32_t sB = A_BYTES + lrow * ROW_BYTES + lcol;

    const int kPerPass = K >> 5;
    const int nIter = 3 * kPerPass;

    const uint32_t aOff = (uint32_t)((warp_m + (lane & 15)) * ROW_BYTES + (lane >> 4) * 16);
    const uint32_t bOff = (uint32_t)(A_BYTES + (warp_n + (lane & 15)) * ROW_BYTES + (lane >> 4) * 16);

    float acc[4][4][4];
#pragma unroll
    for (int i = 0; i < 4; i++)
#pragma unroll
        for (int j = 0; j < 4; j++)
#pragma unroll
            for (int q = 0; q < 4; q++) acc[i][j][q] = 0.f;

    auto issue_stage = [&](int idx) {
        const int p  = idx / kPerPass;
        const int kc = idx - p * kPerPass;
        const size_t offA = (p == 2) ? planeA2 : 0;
        const size_t offB = (p == 1) ? planeB2 : 0;
        const uint32_t st = smBase + (uint32_t)(idx % STAGES) * STAGE_BYTES;
        const char* ga = aRow + offA + kc * 64 + lcol;
        const char* gb = bRow + offB + kc * 64 + lcol;
        cp16(st + sA,      ga,      aok);
        cp16(st + sA + 16, ga + 16, aok);
        cp16(st + sB,      gb,      bok);
        cp16(st + sB + 16, gb + 16, bok);
        CP_COMMIT();
    };

#pragma unroll
    for (int s = 0; s < STAGES - 1; s++) issue_stage(s);

    for (int it = 0; it < nIter; ++it) {
        if (it + STAGES - 1 < nIter) issue_stage(it + STAGES - 1);
        else CP_COMMIT();
        CP_WAIT(STAGES - 2);
        __syncthreads();

        const uint32_t st = smBase + (uint32_t)(it % STAGES) * STAGE_BYTES;
#pragma unroll
        for (int ks = 0; ks < 2; ks++) {
            uint32_t bp0[4], bp1[4];
            LDSM_X4(bp0, st + bOff + ks * 32);
            LDSM_X4(bp1, st + bOff + 1280 + ks * 32);
#pragma unroll
            for (int mf = 0; mf < 4; mf++) {
                uint32_t a[4];
                LDSM_X4(a, st + aOff + mf * 1280 + ks * 32);
                mma_bf16(acc[mf][0], a, bp0[0], bp0[2]);
                mma_bf16(acc[mf][1], a, bp0[1], bp0[3]);
                mma_bf16(acc[mf][2], a, bp1[0], bp1[2]);
                mma_bf16(acc[mf][3], a, bp1[1], bp1[3]);
            }
        }
        __syncthreads();
    }

    // ---------------- epilogue ----------------
    float bs[8], bs2[8];
    if (BN) {
#pragma unroll
        for (int j = 0; j < 8; j++) { bs[j] = 0.f; bs2[j] = 0.f; }
    }

#pragma unroll
    for (int mf = 0; mf < 4; mf++) {
#pragma unroll
        for (int nf = 0; nf < 4; nf++) {
            const int col = n0 + warp_n + nf * 8 + tig * 2;
            if (col >= N) continue;
            float bcol0 = 0.f, bcol1 = 0.f;
            if (BIAS == 1) { bcol0 = bias[col]; bcol1 = bias[col + 1]; }
#pragma unroll
            for (int half = 0; half < 2; half++) {
                const int row = m0 + warp_m + mf * 16 + gid + half * 8;
                if (row >= M) continue;
                float v0 = acc[mf][nf][half * 2 + 0];
                float v1 = acc[mf][nf][half * 2 + 1];
                if (BIAS == 1) { v0 += bcol0; v1 += bcol1; }
                if (BIAS == 2) { float br = bias[row]; v0 += br; v1 += br; }
                if (BN) {
                    bs[nf * 2 + 0] += v0;  bs2[nf * 2 + 0] += v0 * v0;
                    bs[nf * 2 + 1] += v1;  bs2[nf * 2 + 1] += v1 * v1;
                }
                const size_t o = (size_t)row * ldc + col;
                if (Cfb) {
                    *(float2*)(Cfb + o) = make_float2(v0, v1);
                } else {
                    __nv_bfloat16 h0 = __float2bfloat16(v0);
                    __nv_bfloat16 h1 = __float2bfloat16(v1);
                    __nv_bfloat162 hh, ll;
                    hh.x = h0; hh.y = h1;
                    ll.x = __float2bfloat16(v0 - __bfloat162float(h0));
                    ll.y = __float2bfloat16(v1 - __bfloat162float(h1));
                    *(__nv_bfloat162*)(Chb + o) = hh;
                    *(__nv_bfloat162*)(Clb + o) = ll;
                }
            }
        }
    }

    if (BN) {
        // reduce over gid (lanes strided by 4) -> every lane has warp totals
#pragma unroll
        for (int j = 0; j < 8; j++) {
#pragma unroll
            for (int off = 4; off < 32; off <<= 1) {
                bs[j]  += __shfl_xor_sync(0xffffffffu, bs[j],  off);
                bs2[j] += __shfl_xor_sync(0xffffffffu, bs2[j], off);
            }
        }
        __syncthreads();                       // smem stages no longer needed
        float* sum0 = (float*)smraw;           // [2][128] sum, then [2][128] sumsq
        float* sq0  = sum0 + 256;
        if (lane < 4) {
#pragma unroll
            for (int nf = 0; nf < 4; nf++) {
#pragma unroll
                for (int par = 0; par < 2; par++) {
                    int c = warp_n + nf * 8 + tig * 2 + par;   // 0..127
                    sum0[(wid & 1) * 128 + c] = bs[nf * 2 + par];
                    sq0 [(wid & 1) * 128 + c] = bs2[nf * 2 + par];
                }
            }
        }
        __syncthreads();
        if (tid < 128) {
            float s  = sum0[tid] + sum0[128 + tid];
            float s2 = sq0[tid]  + sq0[128 + tid];
            bnPart[(size_t)(n0 + tid) * 2 + 0] = s;
            bnPart[(size_t)(n0 + tid) * 2 + 1] = s2;
        }
    }
}

// =====================================================================
// kernels wrapping gemm_body
// =====================================================================
// merged projections: z = bz*3 + which (0:th 1:ph 2:g)
__global__ void __launch_bounds__(256, 2)
proj_gemm(const __nv_bfloat16* __restrict__ xs1, const __nv_bfloat16* __restrict__ xs2,
          const __nv_bfloat16* __restrict__ thw, const __nv_bfloat16* __restrict__ phw,
          const __nv_bfloat16* __restrict__ gw,
          const float* __restrict__ th_b, const float* __restrict__ ph_b,
          const float* __restrict__ g_b,
          __nv_bfloat16* __restrict__ ths, __nv_bfloat16* __restrict__ phs,
          __nv_bfloat16* __restrict__ gTs)
{
    extern __shared__ __align__(16) uint8_t smraw[];
    const int z = blockIdx.z;
    const int which = z % 3;
    const int bz = z / 3;
    const size_t bX = (size_t)NN * CC;
    const size_t bP = (size_t)NN * CID;

    if (which == 0) {
        gemm_body<1, false>(smraw,
            xs1 + (size_t)bz * bX, CC, P_X * 2,
            thw, CC, P_W * 2,
            NN, CID, CC, th_b,
            nullptr, ths + (size_t)bz * bP, ths + P_P + (size_t)bz * bP,
            CID, blockIdx.y * 128, blockIdx.x * 128, nullptr);
    } else if (which == 1) {
        gemm_body<1, false>(smraw,
            xs2 + (size_t)bz * bX, CC, P_X * 2,
            phw, CC, P_W * 2,
            NN, CID, CC, ph_b,
            nullptr, phs + (size_t)bz * bP, phs + P_P + (size_t)bz * bP,
            CID, blockIdx.y * 128, blockIdx.x * 128, nullptr);
    } else {
        gemm_body<2, false>(smraw,
            gw, CC, P_W * 2,
            xs2 + (size_t)bz * bX, CC, P_X * 2,
            CID, NN, CC, g_b,
            nullptr, gTs + (size_t)bz * bP, gTs + P_P + (size_t)bz * bP,
            NN, blockIdx.x * 128, blockIdx.y * 128, nullptr);
    }
}

template <int BIAS, bool BN>
__global__ void __launch_bounds__(256, 2)
hm_gemm(const __nv_bfloat16* __restrict__ A, int lda, size_t batchA, size_t planeA,
        const __nv_bfloat16* __restrict__ B, int ldb, size_t batchB, size_t planeB,
        int M, int N, int K,
        const float* __restrict__ bias,
        float* __restrict__ Cf,
        __nv_bfloat16* __restrict__ Chi, __nv_bfloat16* __restrict__ Clo,
        int ldc, size_t batchC, float* __restrict__ bnPart)
{
    extern __shared__ __align__(16) uint8_t smraw[];
    const int bz = blockIdx.z;
    const int m0 = blockIdx.y * 128;
    const int n0 = blockIdx.x * 128;
    float* bp = nullptr;
    if (BN) bp = bnPart + ((size_t)bz * NTILE_M + blockIdx.y) * CC * 2;
    gemm_body<BIAS, BN>(smraw,
        A + (size_t)bz * batchA, lda, planeA * 2,
        B + (size_t)bz * batchB, ldb, planeB * 2,
        M, N, K, bias,
        Cf ? Cf + (size_t)bz * batchC : nullptr,
        Chi ? Chi + (size_t)bz * batchC : nullptr,
        Clo ? Clo + (size_t)bz * batchC : nullptr,
        ldc, m0, n0, bp);
}

// =====================================================================
// NCHW -> NHWC transpose + bf16 hi/lo split of x1 and x2 (z selects src)
// =====================================================================
__global__ void __launch_bounds__(256)
split_tr(const float* __restrict__ x1, const float* __restrict__ x2,
         __nv_bfloat16* __restrict__ hi1, __nv_bfloat16* __restrict__ hi2)
{
    __shared__ float t[32][33];
    const int z = blockIdx.z;
    const int b = z & 7;
    const float* x = (z < NB) ? x1 : x2;
    __nv_bfloat16* hi = (z < NB) ? hi1 : hi2;
    const int n0 = blockIdx.x * 32;
    const int c0 = blockIdx.y * 32;
    const int tx = threadIdx.x, ty = threadIdx.y;

    for (int i = ty; i < 32; i += 8)
        t[i][tx] = x[((size_t)b * CC + c0 + i) * NN + n0 + tx];
    __syncthreads();
    for (int i = ty; i < 32; i += 8) {
        float v = t[tx][i];
        size_t o = ((size_t)b * NN + n0 + i) * CC + c0 + tx;
        __nv_bfloat16 h = __float2bfloat16(v);
        hi[o] = h;
        hi[P_X + o] = __float2bfloat16(v - __bfloat162float(h));
    }
}

// all 4 weight splits in one launch (y selects tensor)
__global__ void __launch_bounds__(256)
split_w4(const float* __restrict__ w0, const float* __restrict__ w1,
         const float* __restrict__ w2, const float* __restrict__ w3,
         __nv_bfloat16* __restrict__ h0, __nv_bfloat16* __restrict__ h1,
         __nv_bfloat16* __restrict__ h2, __nv_bfloat16* __restrict__ h3)
{
    const int which = blockIdx.y;
    const float* w = which == 0 ? w0 : which == 1 ? w1 : which == 2 ? w2 : w3;
    __nv_bfloat16* h = which == 0 ? h0 : which == 1 ? h1 : which == 2 ? h2 : h3;
    int i = blockIdx.x * 256 + threadIdx.x;
    if (i < (int)P_W) {
        float v = w[i];
        __nv_bfloat16 hh = __float2bfloat16(v);
        h[i] = hh;
        h[P_W + i] = __float2bfloat16(v - __bfloat162float(hh));
    }
}

// =====================================================================
// Row softmax over NN (vectorized), writes split bf16 attn
// =====================================================================
#define NN4 (NN / 4)   // 784
__global__ void __launch_bounds__(256)
softmax_split(const float* __restrict__ F, __nv_bfloat16* __restrict__ hi,
              __nv_bfloat16* __restrict__ lo)
{
    __shared__ float4 buf[NN4];
    __shared__ float red[256];
    const size_t row = blockIdx.x;
    const float4* __restrict__ p = (const float4*)(F + row * (size_t)NN);
    const int t = threadIdx.x;

    float m = -3.402823466e38f;
    for (int i = t; i < NN4; i += 256) {
        float4 v = p[i];
        buf[i] = v;
        m = fmaxf(fmaxf(m, fmaxf(v.x, v.y)), fmaxf(v.z, v.w));
    }
    red[t] = m; __syncthreads();
    for (int s = 128; s > 0; s >>= 1) {
        if (t < s) red[t] = fmaxf(red[t], red[t + s]);
        __syncthreads();
    }
    m = red[0];
    __syncthreads();

    float sum = 0.f;
    for (int i = t; i < NN4; i += 256) {
        float4 v = buf[i];
        v.x = __expf(v.x - m); v.y = __expf(v.y - m);
        v.z = __expf(v.z - m); v.w = __expf(v.w - m);
        buf[i] = v;
        sum += (v.x + v.y) + (v.z + v.w);
    }
    red[t] = sum; __syncthreads();
    for (int s = 128; s > 0; s >>= 1) {
        if (t < s) red[t] += red[t + s];
        __syncthreads();
    }
    const float inv = 1.f / red[0];
    __nv_bfloat162* __restrict__ hp = (__nv_bfloat162*)(hi + row * (size_t)NN);
    __nv_bfloat162* __restrict__ lp = (__nv_bfloat162*)(lo + row * (size_t)NN);
    for (int i = t; i < NN4; i += 256) {
        float4 v = buf[i];
        float a0 = v.x * inv, a1 = v.y * inv, a2 = v.z * inv, a3 = v.w * inv;
        __nv_bfloat162 h0, h1, l0, l1;
        h0.x = __float2bfloat16(a0); h0.y = __float2bfloat16(a1);
        h1.x = __float2bfloat16(a2); h1.y = __float2bfloat16(a3);
        l0.x = __float2bfloat16(a0 - __bfloat162float(h0.x));
        l0.y = __float2bfloat16(a1 - __bfloat162float(h0.y));
        l1.x = __float2bfloat16(a2 - __bfloat162float(h1.x));
        l1.y = __float2bfloat16(a3 - __bfloat162float(h1.y));
        hp[i * 2] = h0; hp[i * 2 + 1] = h1;
        lp[i * 2] = l0; lp[i * 2 + 1] = l1;
    }
}

// =====================================================================
// BN finalize over fused partials
// =====================================================================
__global__ void __launch_bounds__(256)
bn_finalize(const float* __restrict__ gamma, const float* __restrict__ beta)
{
    int c = blockIdx.x * 256 + threadIdx.x;
    float s = 0.f, s2 = 0.f;
    for (int ch = 0; ch < BN_CHUNKS; ch++) {
        s  += g_part[((size_t)ch * CC + c) * 2 + 0];
        s2 += g_part[((size_t)ch * CC + c) * 2 + 1];
    }
    const float invR = 1.f / (float)ROWS_TOT;
    float mu  = s * invR;
    float var = s2 * invR - mu * mu;
    float a = gamma[c] * rsqrtf(var + 1e-5f);
    g_ab[c * 2 + 0] = a;
    g_ab[c * 2 + 1] = beta[c] - mu * a;
}

// =====================================================================
// normalize + residual + NHWC->NCHW transpose
// =====================================================================
__global__ void __launch_bounds__(256)
out_kernel(const float* __restrict__ wy, const float* __restrict__ x1,
           float* __restrict__ out)
{
    __shared__ float tile[32][33];
    int b  = blockIdx.z;
    int n0 = blockIdx.x * 32;
    int c0 = blockIdx.y * 32;
    int tx = threadIdx.x, ty = threadIdx.y;

    for (int i = ty; i < 32; i += 8) {
        int c = c0 + tx, n = n0 + i;
        float v = wy[((size_t)b * NN + n) * CC + c];
        tile[i][tx] = v * g_ab[c * 2 + 0] + g_ab[c * 2 + 1];
    }
    __syncthreads();
    for (int i = ty; i < 32; i += 8) {
        int c = c0 + i, n = n0 + tx;
        size_t idx = ((size_t)b * CC + c) * (size_t)NN + n;
        out[idx] = tile[tx][i] + x1[idx];
    }
}

// =====================================================================
// launcher
// =====================================================================
extern "C" void kernel_launch(void* const* d_in, const int* in_sizes, int n_in,
                              void* d_out, int out_size)
{
    const float* x1   = (const float*)d_in[0];
    const float* x2   = (const float*)d_in[1];
    const float* g_w  = (const float*)d_in[2];
    const float* g_b  = (const float*)d_in[3];
    const float* th_w = (const float*)d_in[4];
    const float* th_b = (const float*)d_in[5];
    const float* ph_w = (const float*)d_in[6];
    const float* ph_b = (const float*)d_in[7];
    const float* wz_w = (const float*)d_in[8];
    const float* wz_b = (const float*)d_in[9];
    const float* gam  = (const float*)d_in[10];
    const float* bet  = (const float*)d_in[11];
    float* out = (float*)d_out;

    cudaFuncSetAttribute((const void*)proj_gemm,
                         cudaFuncAttributeMaxDynamicSharedMemorySize, SMEM_BYTES);
    cudaFuncSetAttribute((const void*)hm_gemm<0, false>,
                         cudaFuncAttributeMaxDynamicSharedMemorySize, SMEM_BYTES);
    cudaFuncSetAttribute((const void*)hm_gemm<1, true>,
                         cudaFuncAttributeMaxDynamicSharedMemorySize, SMEM_BYTES);

    __nv_bfloat16 *xs1, *xs2, *thw, *phw, *gw, *wzw, *ths, *phs, *gTs, *ys, *as;
    float *f, *wy, *part;
    cudaGetSymbolAddress((void**)&xs1, g_xs1);
    cudaGetSymbolAddress((void**)&xs2, g_xs2);
    cudaGetSymbolAddress((void**)&thw, g_thw);
    cudaGetSymbolAddress((void**)&phw, g_phw);
    cudaGetSymbolAddress((void**)&gw,  g_gw);
    cudaGetSymbolAddress((void**)&wzw, g_wzw);
    cudaGetSymbolAddress((void**)&ths, g_ths);
    cudaGetSymbolAddress((void**)&phs, g_phs);
    cudaGetSymbolAddress((void**)&gTs, g_gTs);
    cudaGetSymbolAddress((void**)&ys,  g_ys);
    cudaGetSymbolAddress((void**)&as,  g_as);
    cudaGetSymbolAddress((void**)&f,   g_f);
    cudaGetSymbolAddress((void**)&wy,  g_wy);
    cudaGetSymbolAddress((void**)&part, g_part);

    dim3 blk256(256);
    dim3 blkT(32, 8);

    // 1) input transpose+split (both tensors, one launch) + weight splits (one launch)
    split_tr<<<dim3(NN / 32, CC / 32, 2 * NB), blkT>>>(x1, x2, xs1, xs2);
    split_w4<<<dim3((int)((P_W + 255) / 256), 4), blk256>>>(
        th_w, ph_w, g_w, wz_w, thw, phw, gw, wzw);

    const size_t bX = (size_t)NN * CC;
    const size_t bP = (size_t)NN * CID;
    const size_t bF = (size_t)NN * NN;

    // 2) all three projections in one launch
    proj_gemm<<<dim3(CID / 128, NTILE_M, NB * 3), blk256, SMEM_BYTES>>>(
        xs1, xs2, thw, phw, gw, th_b, ph_b, g_b, ths, phs, gTs);

    // 3) f = th @ ph^T   -> fp32 (B,N,N)
    hm_gemm<0, false><<<dim3(NTILE_M, NTILE_M, NB), blk256, SMEM_BYTES>>>(
        ths, CID, bP, P_P, phs, CID, bP, P_P,
        NN, NN, CID, nullptr, f, nullptr, nullptr, NN, bF, nullptr);

    // 4) softmax -> split attn
    softmax_split<<<ROWS_TOT, blk256>>>(f, as, as + P_F);

    // 5) y[n,d] = sum_m attn[n,m] gT[d,m]  -> split (B,N,CID)
    hm_gemm<0, false><<<dim3(CID / 128, NTILE_M, NB), blk256, SMEM_BYTES>>>(
        as, NN, bF, P_F, gTs, NN, bP, P_P,
        NN, CID, NN, nullptr, nullptr, ys, ys + P_P, CID, bP, nullptr);

    // 6) wy = y @ wz_w^T + wz_b  -> fp32 (B,N,C), fused BN partials
    hm_gemm<1, true><<<dim3(CC / 128, NTILE_M, NB), blk256, SMEM_BYTES>>>(
        ys, CID, bP, P_P, wzw, CID, 0, P_W,
        NN, CC, CID, wz_b, wy, nullptr, nullptr, CC, (size_t)NN * CC, part);

    // 7) BN finalize + output
    bn_finalize<<<dim3(CC / 256), blk256>>>(gam, bet);
    out_kernel<<<dim3(NN / 32, CC / 32, NB), blkT>>>(wy, x1, out);
}

// round 10
// speedup vs baseline: 3.1210x; 1.0384x over previous
#include <cuda_runtime.h>
#include <cuda_bf16.h>
#include <cstdint>
#include <math.h>

// ---------------- problem constants ----------------
#define NB  8
#define CC  1024
#define CID 512
#define NN  3136
#define ROWS_TOT (NB * NN)
#define NTILE_M 25                 // ceil(3136/128)
#define BN_CHUNKS (NB * NTILE_M)   // 200

// ---------------- device scratch ----------------
static constexpr size_t P_X = (size_t)NB * NN * CC;
static constexpr size_t P_P = (size_t)NB * NN * CID;
static constexpr size_t P_W = (size_t)CID * CC;
static constexpr size_t P_F = (size_t)NB * NN * NN;

__device__ __nv_bfloat16 g_xs1[2 * P_X];
__device__ __nv_bfloat16 g_xs2[2 * P_X];
__device__ __nv_bfloat16 g_thw[2 * P_W];
__device__ __nv_bfloat16 g_phw[2 * P_W];
__device__ __nv_bfloat16 g_gw [2 * P_W];
__device__ __nv_bfloat16 g_wzw[2 * P_W];
__device__ __nv_bfloat16 g_ths[2 * P_P];
__device__ __nv_bfloat16 g_phs[2 * P_P];
__device__ __nv_bfloat16 g_gTs[2 * P_P];
__device__ __nv_bfloat16 g_ys [2 * P_P];
__device__ float g_f[P_F];
__device__ __nv_bfloat16 g_as[2 * P_F];
__device__ float g_wy[(size_t)NB * NN * CC];
__device__ float g_part[(size_t)BN_CHUNKS * CC * 2];
__device__ float g_ab[CC * 2];

// ---------------- mma / ldmatrix / cp.async wrappers ----------------
__device__ __forceinline__ void mma_bf16(float* c, const uint32_t* a,
                                         uint32_t b0, uint32_t b1)
{
    asm volatile(
        "mma.sync.aligned.m16n8k16.row.col.f32.bf16.bf16.f32 "
        "{%0,%1,%2,%3}, {%4,%5,%6,%7}, {%8,%9}, {%0,%1,%2,%3};"
        : "+f"(c[0]), "+f"(c[1]), "+f"(c[2]), "+f"(c[3])
        : "r"(a[0]), "r"(a[1]), "r"(a[2]), "r"(a[3]), "r"(b0), "r"(b1));
}

#define LDSM_X4(r, addr) \
    asm volatile("ldmatrix.sync.aligned.m8n8.x4.shared.b16 {%0,%1,%2,%3}, [%4];" \
        : "=r"((r)[0]), "=r"((r)[1]), "=r"((r)[2]), "=r"((r)[3]) : "r"(addr))

__device__ __forceinline__ void cp16(uint32_t dst, const void* src, int srcsize)
{
    asm volatile("cp.async.cg.shared.global [%0], [%1], 16, %2;"
        :: "r"(dst), "l"(src), "r"(srcsize));
}
#define CP_COMMIT() asm volatile("cp.async.commit_group;" ::: "memory")
#define CP_WAIT(n)  asm volatile("cp.async.wait_group %0;" :: "n"(n) : "memory")

// ---------------- GEMM tiling constants ----------------
#define STAGES 4
#define ROW_BYTES 80
#define A_BYTES (128 * ROW_BYTES)
#define STAGE_BYTES (2 * A_BYTES)
#define SMEM_BYTES (STAGES * STAGE_BYTES)   // 81920

// =====================================================================
// GEMM body: D(M x N) = 3-pass split-bf16 A(M,K) * B(N,K)^T
//   pass 0: A.hi*B.hi   pass 1: A.hi*B.lo   pass 2: A.lo*B.hi
// BIAS: 0 none, 1 col, 2 row.  BN: accumulate column (sum,sumsq) partials.
// Single-barrier multistage mainloop:
//   wait(S-2) -> syncthreads -> issue(it+S-1) -> compute(it)
// (the stage overwritten, (it-1)%S, was fully consumed before the barrier)
// =====================================================================
template <int BIAS, bool BN>
__device__ __forceinline__ void gemm_body(
    uint8_t* smraw,
    const __nv_bfloat16* __restrict__ A, int lda, size_t planeA2,
    const __nv_bfloat16* __restrict__ B, int ldb, size_t planeB2,
    int M, int N, int K,
    const float* __restrict__ bias,
    float* __restrict__ Cfb,
    __nv_bfloat16* __restrict__ Chb, __nv_bfloat16* __restrict__ Clb,
    int ldc, int m0, int n0, float* __restrict__ bnPart)
{
    const uint32_t smBase = (uint32_t)__cvta_generic_to_shared(smraw);
    const int tid  = threadIdx.x;
    const int wid  = tid >> 5;
    const int lane = tid & 31;
    const int gid  = lane >> 2;
    const int tig  = lane & 3;
    const int warp_m = (wid & 1) * 64;
    const int warp_n = (wid >> 1) * 32;

    const int lrow = tid >> 1;
    const int lcol = (tid & 1) * 32;
    const int aok = ((m0 + lrow) < M) ? 16 : 0;
    const int bok = ((n0 + lrow) < N) ? 16 : 0;
    const char* aRow = (const char*)(A + (size_t)(m0 + lrow) * lda);
    const char* bRow = (const char*)(B + (size_t)(n0 + lrow) * ldb);
    const uint32_t sA = lrow * ROW_BYTES + lcol;
    const uint32_t sB = A_BYTES + lrow * ROW_BYTES + lcol;

    const int kPerPass = K >> 5;
    const int nIter = 3 * kPerPass;

    const uint32_t aOff = (uint32_t)((warp_m + (lane & 15)) * ROW_BYTES + (lane >> 4) * 16);
    const uint32_t bOff = (uint32_t)(A_BYTES + (warp_n + (lane & 15)) * ROW_BYTES + (lane >> 4) * 16);

    float acc[4][4][4];
#pragma unroll
    for (int i = 0; i < 4; i++)
#pragma unroll
        for (int j = 0; j < 4; j++)
#pragma unroll
            for (int q = 0; q < 4; q++) acc[i][j][q] = 0.f;

    auto issue_stage = [&](int idx) {
        const int p  = idx / kPerPass;
        const int kc = idx - p * kPerPass;
        const size_t offA = (p == 2) ? planeA2 : 0;
        const size_t offB = (p == 1) ? planeB2 : 0;
        const uint32_t st = smBase + (uint32_t)(idx % STAGES) * STAGE_BYTES;
        const char* ga = aRow + offA + kc * 64 + lcol;
        const char* gb = bRow + offB + kc * 64 + lcol;
        cp16(st + sA,      ga,      aok);
        cp16(st + sA + 16, ga + 16, aok);
        cp16(st + sB,      gb,      bok);
        cp16(st + sB + 16, gb + 16, bok);
        CP_COMMIT();
    };

#pragma unroll
    for (int s = 0; s < STAGES - 1; s++) issue_stage(s);

    for (int it = 0; it < nIter; ++it) {
        CP_WAIT(STAGES - 2);
        __syncthreads();
        if (it + STAGES - 1 < nIter) issue_stage(it + STAGES - 1);
        else CP_COMMIT();                        // keep group count math uniform

        const uint32_t st = smBase + (uint32_t)(it % STAGES) * STAGE_BYTES;
#pragma unroll
        for (int ks = 0; ks < 2; ks++) {
            uint32_t bp0[4], bp1[4];
            LDSM_X4(bp0, st + bOff + ks * 32);
            LDSM_X4(bp1, st + bOff + 1280 + ks * 32);
#pragma unroll
            for (int mf = 0; mf < 4; mf++) {
                uint32_t a[4];
                LDSM_X4(a, st + aOff + mf * 1280 + ks * 32);
                mma_bf16(acc[mf][0], a, bp0[0], bp0[2]);
                mma_bf16(acc[mf][1], a, bp0[1], bp0[3]);
                mma_bf16(acc[mf][2], a, bp1[0], bp1[2]);
                mma_bf16(acc[mf][3], a, bp1[1], bp1[3]);
            }
        }
    }

    // ---------------- epilogue ----------------
    float bs[8], bs2[8];
    if (BN) {
#pragma unroll
        for (int j = 0; j < 8; j++) { bs[j] = 0.f; bs2[j] = 0.f; }
    }

#pragma unroll
    for (int mf = 0; mf < 4; mf++) {
#pragma unroll
        for (int nf = 0; nf < 4; nf++) {
            const int col = n0 + warp_n + nf * 8 + tig * 2;
            if (col >= N) continue;
            float bcol0 = 0.f, bcol1 = 0.f;
            if (BIAS == 1) { bcol0 = bias[col]; bcol1 = bias[col + 1]; }
#pragma unroll
            for (int half = 0; half < 2; half++) {
                const int row = m0 + warp_m + mf * 16 + gid + half * 8;
                if (row >= M) continue;
                float v0 = acc[mf][nf][half * 2 + 0];
                float v1 = acc[mf][nf][half * 2 + 1];
                if (BIAS == 1) { v0 += bcol0; v1 += bcol1; }
                if (BIAS == 2) { float br = bias[row]; v0 += br; v1 += br; }
                if (BN) {
                    bs[nf * 2 + 0] += v0;  bs2[nf * 2 + 0] += v0 * v0;
                    bs[nf * 2 + 1] += v1;  bs2[nf * 2 + 1] += v1 * v1;
                }
                const size_t o = (size_t)row * ldc + col;
                if (Cfb) {
                    *(float2*)(Cfb + o) = make_float2(v0, v1);
                } else {
                    __nv_bfloat16 h0 = __float2bfloat16(v0);
                    __nv_bfloat16 h1 = __float2bfloat16(v1);
                    __nv_bfloat162 hh, ll;
                    hh.x = h0; hh.y = h1;
                    ll.x = __float2bfloat16(v0 - __bfloat162float(h0));
                    ll.y = __float2bfloat16(v1 - __bfloat162float(h1));
                    *(__nv_bfloat162*)(Chb + o) = hh;
                    *(__nv_bfloat162*)(Clb + o) = ll;
                }
            }
        }
    }

    if (BN) {
#pragma unroll
        for (int j = 0; j < 8; j++) {
#pragma unroll
            for (int off = 4; off < 32; off <<= 1) {
                bs[j]  += __shfl_xor_sync(0xffffffffu, bs[j],  off);
                bs2[j] += __shfl_xor_sync(0xffffffffu, bs2[j], off);
            }
        }
        __syncthreads();
        float* sum0 = (float*)smraw;
        float* sq0  = sum0 + 256;
        if (lane < 4) {
#pragma unroll
            for (int nf = 0; nf < 4; nf++) {
#pragma unroll
                for (int par = 0; par < 2; par++) {
                    int c = warp_n + nf * 8 + tig * 2 + par;
                    sum0[(wid & 1) * 128 + c] = bs[nf * 2 + par];
                    sq0 [(wid & 1) * 128 + c] = bs2[nf * 2 + par];
                }
            }
        }
        __syncthreads();
        if (tid < 128) {
            float s  = sum0[tid] + sum0[128 + tid];
            float s2 = sq0[tid]  + sq0[128 + tid];
            bnPart[(size_t)(n0 + tid) * 2 + 0] = s;
            bnPart[(size_t)(n0 + tid) * 2 + 1] = s2;
        }
    }
}

// =====================================================================
// kernels wrapping gemm_body
// =====================================================================
__global__ void __launch_bounds__(256, 2)
proj_gemm(const __nv_bfloat16* __restrict__ xs1, const __nv_bfloat16* __restrict__ xs2,
          const __nv_bfloat16* __restrict__ thw, const __nv_bfloat16* __restrict__ phw,
          const __nv_bfloat16* __restrict__ gw,
          const float* __restrict__ th_b, const float* __restrict__ ph_b,
          const float* __restrict__ g_b,
          __nv_bfloat16* __restrict__ ths, __nv_bfloat16* __restrict__ phs,
          __nv_bfloat16* __restrict__ gTs)
{
    extern __shared__ __align__(16) uint8_t smraw[];
    const int z = blockIdx.z;
    const int which = z % 3;
    const int bz = z / 3;
    const size_t bX = (size_t)NN * CC;
    const size_t bP = (size_t)NN * CID;

    if (which == 0) {
        gemm_body<1, false>(smraw,
            xs1 + (size_t)bz * bX, CC, P_X * 2,
            thw, CC, P_W * 2,
            NN, CID, CC, th_b,
            nullptr, ths + (size_t)bz * bP, ths + P_P + (size_t)bz * bP,
            CID, blockIdx.y * 128, blockIdx.x * 128, nullptr);
    } else if (which == 1) {
        gemm_body<1, false>(smraw,
            xs2 + (size_t)bz * bX, CC, P_X * 2,
            phw, CC, P_W * 2,
            NN, CID, CC, ph_b,
            nullptr, phs + (size_t)bz * bP, phs + P_P + (size_t)bz * bP,
            CID, blockIdx.y * 128, blockIdx.x * 128, nullptr);
    } else {
        gemm_body<2, false>(smraw,
            gw, CC, P_W * 2,
            xs2 + (size_t)bz * bX, CC, P_X * 2,
            CID, NN, CC, g_b,
            nullptr, gTs + (size_t)bz * bP, gTs + P_P + (size_t)bz * bP,
            NN, blockIdx.x * 128, blockIdx.y * 128, nullptr);
    }
}

template <int BIAS, bool BN>
__global__ void __launch_bounds__(256, 2)
hm_gemm(const __nv_bfloat16* __restrict__ A, int lda, size_t batchA, size_t planeA,
        const __nv_bfloat16* __restrict__ B, int ldb, size_t batchB, size_t planeB,
        int M, int N, int K,
        const float* __restrict__ bias,
        float* __restrict__ Cf,
        __nv_bfloat16* __restrict__ Chi, __nv_bfloat16* __restrict__ Clo,
        int ldc, size_t batchC, float* __restrict__ bnPart)
{
    extern __shared__ __align__(16) uint8_t smraw[];
    const int bz = blockIdx.z;
    const int m0 = blockIdx.y * 128;
    const int n0 = blockIdx.x * 128;
    float* bp = nullptr;
    if (BN) bp = bnPart + ((size_t)bz * NTILE_M + blockIdx.y) * CC * 2;
    gemm_body<BIAS, BN>(smraw,
        A + (size_t)bz * batchA, lda, planeA * 2,
        B + (size_t)bz * batchB, ldb, planeB * 2,
        M, N, K, bias,
        Cf ? Cf + (size_t)bz * batchC : nullptr,
        Chi ? Chi + (size_t)bz * batchC : nullptr,
        Clo ? Clo + (size_t)bz * batchC : nullptr,
        ldc, m0, n0, bp);
}

// =====================================================================
// NCHW -> NHWC transpose + bf16 hi/lo split of x1 and x2 (z selects src)
// =====================================================================
__global__ void __launch_bounds__(256)
split_tr(const float* __restrict__ x1, const float* __restrict__ x2,
         __nv_bfloat16* __restrict__ hi1, __nv_bfloat16* __restrict__ hi2)
{
    __shared__ float t[32][33];
    const int z = blockIdx.z;
    const int b = z & 7;
    const float* x = (z < NB) ? x1 : x2;
    __nv_bfloat16* hi = (z < NB) ? hi1 : hi2;
    const int n0 = blockIdx.x * 32;
    const int c0 = blockIdx.y * 32;
    const int tx = threadIdx.x, ty = threadIdx.y;

    for (int i = ty; i < 32; i += 8)
        t[i][tx] = x[((size_t)b * CC + c0 + i) * NN + n0 + tx];
    __syncthreads();
    for (int i = ty; i < 32; i += 8) {
        float v = t[tx][i];
        size_t o = ((size_t)b * NN + n0 + i) * CC + c0 + tx;
        __nv_bfloat16 h = __float2bfloat16(v);
        hi[o] = h;
        hi[P_X + o] = __float2bfloat16(v - __bfloat162float(h));
    }
}

__global__ void __launch_bounds__(256)
split_w4(const float* __restrict__ w0, const float* __restrict__ w1,
         const float* __restrict__ w2, const float* __restrict__ w3,
         __nv_bfloat16* __restrict__ h0, __nv_bfloat16* __restrict__ h1,
         __nv_bfloat16* __restrict__ h2, __nv_bfloat16* __restrict__ h3)
{
    const int which = blockIdx.y;
    const float* w = which == 0 ? w0 : which == 1 ? w1 : which == 2 ? w2 : w3;
    __nv_bfloat16* h = which == 0 ? h0 : which == 1 ? h1 : which == 2 ? h2 : h3;
    int i = blockIdx.x * 256 + threadIdx.x;
    if (i < (int)P_W) {
        float v = w[i];
        __nv_bfloat16 hh = __float2bfloat16(v);
        h[i] = hh;
        h[P_W + i] = __float2bfloat16(v - __bfloat162float(hh));
    }
}

// =====================================================================
// Row softmax over NN (vectorized), writes split bf16 attn
// =====================================================================
#define NN4 (NN / 4)   // 784
__global__ void __launch_bounds__(256)
softmax_split(const float* __restrict__ F, __nv_bfloat16* __restrict__ hi,
              __nv_bfloat16* __restrict__ lo)
{
    __shared__ float4 buf[NN4];
    __shared__ float red[256];
    const size_t row = blockIdx.x;
    const float4* __restrict__ p = (const float4*)(F + row * (size_t)NN);
    const int t = threadIdx.x;

    float m = -3.402823466e38f;
    for (int i = t; i < NN4; i += 256) {
        float4 v = p[i];
        buf[i] = v;
        m = fmaxf(fmaxf(m, fmaxf(v.x, v.y)), fmaxf(v.z, v.w));
    }
    red[t] = m; __syncthreads();
    for (int s = 128; s > 0; s >>= 1) {
        if (t < s) red[t] = fmaxf(red[t], red[t + s]);
        __syncthreads();
    }
    m = red[0];
    __syncthreads();

    float sum = 0.f;
    for (int i = t; i < NN4; i += 256) {
        float4 v = buf[i];
        v.x = __expf(v.x - m); v.y = __expf(v.y - m);
        v.z = __expf(v.z - m); v.w = __expf(v.w - m);
        buf[i] = v;
        sum += (v.x + v.y) + (v.z + v.w);
    }
    red[t] = sum; __syncthreads();
    for (int s = 128; s > 0; s >>= 1) {
        if (t < s) red[t] += red[t + s];
        __syncthreads();
    }
    const float inv = 1.f / red[0];
    __nv_bfloat162* __restrict__ hp = (__nv_bfloat162*)(hi + row * (size_t)NN);
    __nv_bfloat162* __restrict__ lp = (__nv_bfloat162*)(lo + row * (size_t)NN);
    for (int i = t; i < NN4; i += 256) {
        float4 v = buf[i];
        float a0 = v.x * inv, a1 = v.y * inv, a2 = v.z * inv, a3 = v.w * inv;
        __nv_bfloat162 h0, h1, l0, l1;
        h0.x = __float2bfloat16(a0); h0.y = __float2bfloat16(a1);
        h1.x = __float2bfloat16(a2); h1.y = __float2bfloat16(a3);
        l0.x = __float2bfloat16(a0 - __bfloat162float(h0.x));
        l0.y = __float2bfloat16(a1 - __bfloat162float(h0.y));
        l1.x = __float2bfloat16(a2 - __bfloat162float(h1.x));
        l1.y = __float2bfloat16(a3 - __bfloat162float(h1.y));
        hp[i * 2] = h0; hp[i * 2 + 1] = h1;
        lp[i * 2] = l0; lp[i * 2 + 1] = l1;
    }
}

// =====================================================================
// BN finalize over fused partials
// =====================================================================
__global__ void __launch_bounds__(256)
bn_finalize(const float* __restrict__ gamma, const float* __restrict__ beta)
{
    int c = blockIdx.x * 256 + threadIdx.x;
    float s = 0.f, s2 = 0.f;
    for (int ch = 0; ch < BN_CHUNKS; ch++) {
        s  += g_part[((size_t)ch * CC + c) * 2 + 0];
        s2 += g_part[((size_t)ch * CC + c) * 2 + 1];
    }
    const float invR = 1.f / (float)ROWS_TOT;
    float mu  = s * invR;
    float var = s2 * invR - mu * mu;
    float a = gamma[c] * rsqrtf(var + 1e-5f);
    g_ab[c * 2 + 0] = a;
    g_ab[c * 2 + 1] = beta[c] - mu * a;
}

// =====================================================================
// normalize + residual + NHWC->NCHW transpose
// =====================================================================
__global__ void __launch_bounds__(256)
out_kernel(const float* __restrict__ wy, const float* __restrict__ x1,
           float* __restrict__ out)
{
    __shared__ float tile[32][33];
    int b  = blockIdx.z;
    int n0 = blockIdx.x * 32;
    int c0 = blockIdx.y * 32;
    int tx = threadIdx.x, ty = threadIdx.y;

    for (int i = ty; i < 32; i += 8) {
        int c = c0 + tx, n = n0 + i;
        float v = wy[((size_t)b * NN + n) * CC + c];
        tile[i][tx] = v * g_ab[c * 2 + 0] + g_ab[c * 2 + 1];
    }
    __syncthreads();
    for (int i = ty; i < 32; i += 8) {
        int c = c0 + i, n = n0 + tx;
        size_t idx = ((size_t)b * CC + c) * (size_t)NN + n;
        out[idx] = tile[tx][i] + x1[idx];
    }
}

// =====================================================================
// launcher
// =====================================================================
extern "C" void kernel_launch(void* const* d_in, const int* in_sizes, int n_in,
                              void* d_out, int out_size)
{
    const float* x1   = (const float*)d_in[0];
    const float* x2   = (const float*)d_in[1];
    const float* g_w  = (const float*)d_in[2];
    const float* g_b  = (const float*)d_in[3];
    const float* th_w = (const float*)d_in[4];
    const float* th_b = (const float*)d_in[5];
    const float* ph_w = (const float*)d_in[6];
    const float* ph_b = (const float*)d_in[7];
    const float* wz_w = (const float*)d_in[8];
    const float* wz_b = (const float*)d_in[9];
    const float* gam  = (const float*)d_in[10];
    const float* bet  = (const float*)d_in[11];
    float* out = (float*)d_out;

    cudaFuncSetAttribute((const void*)proj_gemm,
                         cudaFuncAttributeMaxDynamicSharedMemorySize, SMEM_BYTES);
    cudaFuncSetAttribute((const void*)hm_gemm<0, false>,
                         cudaFuncAttributeMaxDynamicSharedMemorySize, SMEM_BYTES);
    cudaFuncSetAttribute((const void*)hm_gemm<1, true>,
                         cudaFuncAttributeMaxDynamicSharedMemorySize, SMEM_BYTES);

    __nv_bfloat16 *xs1, *xs2, *thw, *phw, *gw, *wzw, *ths, *phs, *gTs, *ys, *as;
    float *f, *wy, *part;
    cudaGetSymbolAddress((void**)&xs1, g_xs1);
    cudaGetSymbolAddress((void**)&xs2, g_xs2);
    cudaGetSymbolAddress((void**)&thw, g_thw);
    cudaGetSymbolAddress((void**)&phw, g_phw);
    cudaGetSymbolAddress((void**)&gw,  g_gw);
    cudaGetSymbolAddress((void**)&wzw, g_wzw);
    cudaGetSymbolAddress((void**)&ths, g_ths);
    cudaGetSymbolAddress((void**)&phs, g_phs);
    cudaGetSymbolAddress((void**)&gTs, g_gTs);
    cudaGetSymbolAddress((void**)&ys,  g_ys);
    cudaGetSymbolAddress((void**)&as,  g_as);
    cudaGetSymbolAddress((void**)&f,   g_f);
    cudaGetSymbolAddress((void**)&wy,  g_wy);
    cudaGetSymbolAddress((void**)&part, g_part);

    dim3 blk256(256);
    dim3 blkT(32, 8);

    split_tr<<<dim3(NN / 32, CC / 32, 2 * NB), blkT>>>(x1, x2, xs1, xs2);
    split_w4<<<dim3((int)((P_W + 255) / 256), 4), blk256>>>(
        th_w, ph_w, g_w, wz_w, thw, phw, gw, wzw);

    const size_t bP = (size_t)NN * CID;
    const size_t bF = (size_t)NN * NN;

    proj_gemm<<<dim3(CID / 128, NTILE_M, NB * 3), blk256, SMEM_BYTES>>>(
        xs1, xs2, thw, phw, gw, th_b, ph_b, g_b, ths, phs, gTs);

    hm_gemm<0, false><<<dim3(NTILE_M, NTILE_M, NB), blk256, SMEM_BYTES>>>(
        ths, CID, bP, P_P, phs, CID, bP, P_P,
        NN, NN, CID, nullptr, f, nullptr, nullptr, NN, bF, nullptr);

    softmax_split<<<ROWS_TOT, blk256>>>(f, as, as + P_F);

    hm_gemm<0, false><<<dim3(CID / 128, NTILE_M, NB), blk256, SMEM_BYTES>>>(
        as, NN, bF, P_F, gTs, NN, bP, P_P,
        NN, CID, NN, nullptr, nullptr, ys, ys + P_P, CID, bP, nullptr);

    hm_gemm<1, true><<<dim3(CC / 128, NTILE_M, NB), blk256, SMEM_BYTES>>>(
        ys, CID, bP, P_P, wzw, CID, 0, P_W,
        NN, CC, CID, wz_b, wy, nullptr, nullptr, CC, (size_t)NN * CC, part);

    bn_finalize<<<dim3(CC / 256), blk256>>>(gam, bet);
    out_kernel<<<dim3(NN / 32, CC / 32, NB), blkT>>>(wy, x1, out);
}